// round 1
// baseline (speedup 1.0000x reference)
#include <cuda_runtime.h>
#include <math.h>

#define DIM 1024
#define NH 16
#define HD 64
#define BATCH 2
#define SEQ 2048
#define MTOT (BATCH * SEQ)   // 4096

// Scratch (device globals: allowed; no runtime allocation)
__device__ float g_xq[MTOT * DIM];
__device__ float g_xk[MTOT * DIM];
__device__ float g_xv[MTOT * DIM];
__device__ float g_xo[MTOT * DIM];

// ---------------------------------------------------------------------------
// NT GEMM: C[M,N] = A[M,K] @ W[N,K]^T   (both row-major, K contiguous)
// Tile 64x64, BK=16, 256 threads, 4x4 micro-tile per thread.
// ---------------------------------------------------------------------------
__global__ void __launch_bounds__(256) gemm_nt_kernel(
    const float* __restrict__ A, const float* __restrict__ W,
    float* __restrict__ C, int M, int N, int K)
{
    __shared__ float As[64][17];
    __shared__ float Ws[64][17];

    const int tid = threadIdx.x;
    const int tx = tid & 15;
    const int ty = tid >> 4;
    const int bm = blockIdx.y * 64;
    const int bn = blockIdx.x * 64;

    const int lr = tid >> 2;            // 0..63
    const int lc = (tid & 3) << 2;      // 0,4,8,12

    const float* Ap = A + (size_t)(bm + lr) * K + lc;
    const float* Wp = W + (size_t)(bn + lr) * K + lc;

    float acc[4][4] = {};

    for (int k0 = 0; k0 < K; k0 += 16) {
        float4 a = *(const float4*)(Ap + k0);
        float4 w = *(const float4*)(Wp + k0);
        As[lr][lc + 0] = a.x; As[lr][lc + 1] = a.y;
        As[lr][lc + 2] = a.z; As[lr][lc + 3] = a.w;
        Ws[lr][lc + 0] = w.x; Ws[lr][lc + 1] = w.y;
        Ws[lr][lc + 2] = w.z; Ws[lr][lc + 3] = w.w;
        __syncthreads();

#pragma unroll
        for (int k = 0; k < 16; k++) {
            float ar[4], wr[4];
#pragma unroll
            for (int i = 0; i < 4; i++) ar[i] = As[ty * 4 + i][k];
#pragma unroll
            for (int j = 0; j < 4; j++) wr[j] = Ws[tx * 4 + j][k];
#pragma unroll
            for (int i = 0; i < 4; i++)
#pragma unroll
                for (int j = 0; j < 4; j++)
                    acc[i][j] = fmaf(ar[i], wr[j], acc[i][j]);
        }
        __syncthreads();
    }

#pragma unroll
    for (int i = 0; i < 4; i++)
#pragma unroll
        for (int j = 0; j < 4; j++)
            C[(size_t)(bm + ty * 4 + i) * N + bn + tx * 4 + j] = acc[i][j];
}

// ---------------------------------------------------------------------------
// Flash attention (causal, online softmax).
// One CTA per (b,h, q-tile of 64 rows). KV tiles of 64. 256 threads.
// Layouts: xq/xk/xv/xo are [B*S, DIM], head h occupies cols [h*64, h*64+64).
// Smem: Qs[64][65], Ks[64][65] (reused as P), Vs[64][65], rowm/rowl/rowa[64].
// ---------------------------------------------------------------------------
#define QT 64
#define KT 64
#define LDA 65

__global__ void __launch_bounds__(256) flash_attn_kernel(
    const float* __restrict__ xq, const float* __restrict__ xk,
    const float* __restrict__ xv, float* __restrict__ xo)
{
    extern __shared__ float sm[];
    float* Qs   = sm;                    // QT * LDA
    float* Ks   = Qs + QT * LDA;         // KT * LDA  (reused as P tile)
    float* Vs   = Ks + KT * LDA;         // KT * LDA
    float* rowm = Vs + KT * LDA;         // QT
    float* rowl = rowm + QT;             // QT
    float* rowa = rowl + QT;             // QT

    const int tid = threadIdx.x;
    const int tx = tid & 15;
    const int ty = tid >> 4;
    const int bh = blockIdx.y;
    const int b = bh >> 4;
    const int h = bh & 15;
    const int qt = blockIdx.x;

    const size_t base = (size_t)b * SEQ * DIM + (size_t)h * HD;

    // Load Q tile: 64 rows x 64 cols, 4x float4 per thread.
    {
        const int r = tid >> 2;
        const int c0 = (tid & 3) << 4;   // 0,16,32,48
        const float* src = xq + base + (size_t)(qt * QT + r) * DIM + c0;
        float* dst = Qs + r * LDA + c0;
#pragma unroll
        for (int f = 0; f < 4; f++) {
            float4 v = *(const float4*)(src + f * 4);
            dst[f * 4 + 0] = v.x; dst[f * 4 + 1] = v.y;
            dst[f * 4 + 2] = v.z; dst[f * 4 + 3] = v.w;
        }
    }
    if (tid < QT) { rowm[tid] = -1e30f; rowl[tid] = 0.0f; }

    float o[4][4] = {};
    __syncthreads();

    for (int kt = 0; kt <= qt; kt++) {
        // Load K and V tiles
        {
            const int r = tid >> 2;
            const int c0 = (tid & 3) << 4;
            const float* ks = xk + base + (size_t)(kt * KT + r) * DIM + c0;
            const float* vs = xv + base + (size_t)(kt * KT + r) * DIM + c0;
            float* kd = Ks + r * LDA + c0;
            float* vd = Vs + r * LDA + c0;
#pragma unroll
            for (int f = 0; f < 4; f++) {
                float4 kv = *(const float4*)(ks + f * 4);
                kd[f * 4 + 0] = kv.x; kd[f * 4 + 1] = kv.y;
                kd[f * 4 + 2] = kv.z; kd[f * 4 + 3] = kv.w;
                float4 vv = *(const float4*)(vs + f * 4);
                vd[f * 4 + 0] = vv.x; vd[f * 4 + 1] = vv.y;
                vd[f * 4 + 2] = vv.z; vd[f * 4 + 3] = vv.w;
            }
        }
        __syncthreads();

        // S = Q @ K^T  (4x4 per thread)
        float s[4][4] = {};
#pragma unroll 16
        for (int d = 0; d < HD; d++) {
            float qr[4], kr[4];
#pragma unroll
            for (int i = 0; i < 4; i++) qr[i] = Qs[(ty * 4 + i) * LDA + d];
#pragma unroll
            for (int j = 0; j < 4; j++) kr[j] = Ks[(tx * 4 + j) * LDA + d];
#pragma unroll
            for (int i = 0; i < 4; i++)
#pragma unroll
                for (int j = 0; j < 4; j++)
                    s[i][j] = fmaf(qr[i], kr[j], s[i][j]);
        }

        // Scale + causal mask (only diagonal tile needs masking)
        if (kt == qt) {
#pragma unroll
            for (int i = 0; i < 4; i++)
#pragma unroll
                for (int j = 0; j < 4; j++)
                    s[i][j] = (tx * 4 + j > ty * 4 + i) ? -1e30f
                                                        : s[i][j] * 0.125f;
        } else {
#pragma unroll
            for (int i = 0; i < 4; i++)
#pragma unroll
                for (int j = 0; j < 4; j++)
                    s[i][j] *= 0.125f;
        }

        __syncthreads();   // everyone done reading Ks

        // Store S into Ks buffer (now P-tile storage)
#pragma unroll
        for (int i = 0; i < 4; i++)
#pragma unroll
            for (int j = 0; j < 4; j++)
                Ks[(ty * 4 + i) * LDA + tx * 4 + j] = s[i][j];
        __syncthreads();

        // Per-row online softmax update (64 threads, one per row)
        if (tid < QT) {
            const int r = tid;
            float mx = rowm[r];
#pragma unroll 8
            for (int j = 0; j < KT; j++) mx = fmaxf(mx, Ks[r * LDA + j]);
            const float alpha = __expf(rowm[r] - mx);
            float l = rowl[r] * alpha;
#pragma unroll 8
            for (int j = 0; j < KT; j++) {
                const float p = __expf(Ks[r * LDA + j] - mx);
                Ks[r * LDA + j] = p;
                l += p;
            }
            rowm[r] = mx; rowl[r] = l; rowa[r] = alpha;
        }
        __syncthreads();

        // Rescale O, accumulate O += P @ V
        {
            float al[4];
#pragma unroll
            for (int i = 0; i < 4; i++) al[i] = rowa[ty * 4 + i];
#pragma unroll
            for (int i = 0; i < 4; i++)
#pragma unroll
                for (int j = 0; j < 4; j++)
                    o[i][j] *= al[i];
        }
#pragma unroll 16
        for (int kk = 0; kk < KT; kk++) {
            float p[4], v[4];
#pragma unroll
            for (int i = 0; i < 4; i++) p[i] = Ks[(ty * 4 + i) * LDA + kk];
#pragma unroll
            for (int j = 0; j < 4; j++) v[j] = Vs[kk * LDA + tx * 4 + j];
#pragma unroll
            for (int i = 0; i < 4; i++)
#pragma unroll
                for (int j = 0; j < 4; j++)
                    o[i][j] = fmaf(p[i], v[j], o[i][j]);
        }
        __syncthreads();   // before next tile overwrites Ks/Vs
    }

    // Normalize and write out (directly in [B*S, DIM] layout → no transpose pass)
    float inv[4];
#pragma unroll
    for (int i = 0; i < 4; i++) inv[i] = 1.0f / rowl[ty * 4 + i];
#pragma unroll
    for (int i = 0; i < 4; i++)
#pragma unroll
        for (int j = 0; j < 4; j++)
            xo[base + (size_t)(qt * QT + ty * 4 + i) * DIM + tx * 4 + j] =
                o[i][j] * inv[i];
}

// ---------------------------------------------------------------------------
// Launch
// ---------------------------------------------------------------------------
extern "C" void kernel_launch(void* const* d_in, const int* in_sizes, int n_in,
                              void* d_out, int out_size)
{
    const float* q  = (const float*)d_in[0];
    const float* k  = (const float*)d_in[1];
    const float* v  = (const float*)d_in[2];
    const float* wq = (const float*)d_in[3];
    const float* wk = (const float*)d_in[4];
    const float* wv = (const float*)d_in[5];
    const float* wo = (const float*)d_in[6];
    float* out = (float*)d_out;

    float *xq, *xk, *xv, *xo;
    cudaGetSymbolAddress((void**)&xq, g_xq);
    cudaGetSymbolAddress((void**)&xk, g_xk);
    cudaGetSymbolAddress((void**)&xv, g_xv);
    cudaGetSymbolAddress((void**)&xo, g_xo);

    const int flash_smem = (3 * QT * LDA + 3 * QT) * (int)sizeof(float);
    cudaFuncSetAttribute(flash_attn_kernel,
                         cudaFuncAttributeMaxDynamicSharedMemorySize,
                         flash_smem);

    dim3 gemm_grid(DIM / 64, MTOT / 64);   // (16, 64)
    gemm_nt_kernel<<<gemm_grid, 256>>>(q, wq, xq, MTOT, DIM, DIM);
    gemm_nt_kernel<<<gemm_grid, 256>>>(k, wk, xk, MTOT, DIM, DIM);
    gemm_nt_kernel<<<gemm_grid, 256>>>(v, wv, xv, MTOT, DIM, DIM);

    dim3 flash_grid(SEQ / QT, BATCH * NH); // (32, 32)
    flash_attn_kernel<<<flash_grid, 256, flash_smem>>>(xq, xk, xv, xo);

    gemm_nt_kernel<<<gemm_grid, 256>>>(xo, wo, out, MTOT, DIM, DIM);
}

// round 2
// speedup vs baseline: 2.4805x; 2.4805x over previous
#include <cuda_runtime.h>
#include <math.h>

#define DIM 1024
#define NH 16
#define HD 64
#define BATCH 2
#define SEQ 2048
#define MTOT (BATCH * SEQ)   // 4096

// Scratch (device globals: allowed; no runtime allocation)
__device__ float g_xq[MTOT * DIM];
__device__ float g_xk[MTOT * DIM];
__device__ float g_xv[MTOT * DIM];
__device__ float g_xo[MTOT * DIM];

__device__ __forceinline__ unsigned f2tf(float x) {
    unsigned r;
    asm("cvt.rna.tf32.f32 %0, %1;" : "=r"(r) : "f"(x));
    return r;
}

__device__ __forceinline__ void mma_tf32(float* c, const unsigned* a, const unsigned* b) {
    asm volatile(
        "mma.sync.aligned.m16n8k8.row.col.f32.tf32.tf32.f32 "
        "{%0,%1,%2,%3}, {%4,%5,%6,%7}, {%8,%9}, {%0,%1,%2,%3};\n"
        : "+f"(c[0]), "+f"(c[1]), "+f"(c[2]), "+f"(c[3])
        : "r"(a[0]), "r"(a[1]), "r"(a[2]), "r"(a[3]), "r"(b[0]), "r"(b[1]));
}

// ---------------------------------------------------------------------------
// TF32 NT GEMM: C[M,N] = A[M,K] @ W[N,K]^T
// 128x128x32 tile, 256 threads (8 warps, 4x2), warp tile 32x64.
// smem ld=36 -> frag addr pattern (4g+t) mod 32: conflict-free.
// ---------------------------------------------------------------------------
#define GLD 36

__global__ void __launch_bounds__(256, 2) gemm_tc(
    const float* __restrict__ A, const float* __restrict__ W,
    float* __restrict__ C, int M, int N, int K)
{
    __shared__ unsigned As[128 * GLD];
    __shared__ unsigned Ws[128 * GLD];

    const int tid = threadIdx.x;
    const int warp = tid >> 5, lane = tid & 31;
    const int g = lane >> 2, t = lane & 3;
    const int wm = (warp >> 1) * 32, wn = (warp & 1) * 64;
    const int bm = blockIdx.y * 128, bn = blockIdx.x * 128;

    const int lrow = tid >> 1;
    const int lcol = (tid & 1) * 16;
    const float* Ap = A + (size_t)(bm + lrow) * K + lcol;
    const float* Wp = W + (size_t)(bn + lrow) * K + lcol;
    unsigned* Asd = As + lrow * GLD + lcol;
    unsigned* Wsd = Ws + lrow * GLD + lcol;

    float acc[2][8][4] = {};

    for (int k0 = 0; k0 < K; k0 += 32) {
#pragma unroll
        for (int f = 0; f < 4; f++) {
            float4 a = *(const float4*)(Ap + k0 + f * 4);
            Asd[f * 4 + 0] = f2tf(a.x); Asd[f * 4 + 1] = f2tf(a.y);
            Asd[f * 4 + 2] = f2tf(a.z); Asd[f * 4 + 3] = f2tf(a.w);
            float4 w = *(const float4*)(Wp + k0 + f * 4);
            Wsd[f * 4 + 0] = f2tf(w.x); Wsd[f * 4 + 1] = f2tf(w.y);
            Wsd[f * 4 + 2] = f2tf(w.z); Wsd[f * 4 + 3] = f2tf(w.w);
        }
        __syncthreads();

#pragma unroll
        for (int ks = 0; ks < 4; ks++) {
            unsigned afr[2][4], bfr[8][2];
#pragma unroll
            for (int mt = 0; mt < 2; mt++) {
                const unsigned* p = As + (wm + mt * 16 + g) * GLD + ks * 8 + t;
                afr[mt][0] = p[0];
                afr[mt][1] = p[8 * GLD];
                afr[mt][2] = p[4];
                afr[mt][3] = p[8 * GLD + 4];
            }
#pragma unroll
            for (int nt = 0; nt < 8; nt++) {
                const unsigned* p = Ws + (wn + nt * 8 + g) * GLD + ks * 8 + t;
                bfr[nt][0] = p[0];
                bfr[nt][1] = p[4];
            }
#pragma unroll
            for (int mt = 0; mt < 2; mt++)
#pragma unroll
                for (int nt = 0; nt < 8; nt++)
                    mma_tf32(acc[mt][nt], afr[mt], bfr[nt]);
        }
        __syncthreads();
    }

#pragma unroll
    for (int mt = 0; mt < 2; mt++)
#pragma unroll
        for (int nt = 0; nt < 8; nt++) {
            const int row = bm + wm + mt * 16 + g;
            const int col = bn + wn + nt * 8 + 2 * t;
            *(float2*)&C[(size_t)row * N + col] =
                make_float2(acc[mt][nt][0], acc[mt][nt][1]);
            *(float2*)&C[(size_t)(row + 8) * N + col] =
                make_float2(acc[mt][nt][2], acc[mt][nt][3]);
        }
}

// ---------------------------------------------------------------------------
// TF32 flash attention (causal, online softmax, warp-local rows).
// CTA: 64 q-rows (4 warps x 16 rows), KV tiles of 64.
// Each warp owns the full 64-wide KV strip for its rows -> softmax needs only
// intra-quad shuffles; P goes through per-warp smem (syncwarp only).
// Q fragments live in registers for the whole KV loop; 1/8 folded into Q.
// ---------------------------------------------------------------------------
#define FQ 64
#define FK 64
#define LDK 68   // (4g+t) pattern: conflict-free for K/P frag loads
#define LDV 72   // (8t+g) pattern: conflict-free for V frag loads
#define LDP 68

__global__ void __launch_bounds__(128, 3) flash_tc(
    const float* __restrict__ xq, const float* __restrict__ xk,
    const float* __restrict__ xv, float* __restrict__ xo)
{
    extern __shared__ unsigned sm[];
    unsigned* Ks = sm;                 // FK*LDK
    unsigned* Vs = Ks + FK * LDK;      // FK*LDV
    unsigned* Ps = Vs + FK * LDV;      // FQ*LDP

    const int tid = threadIdx.x;
    const int warp = tid >> 5, lane = tid & 31;
    const int g = lane >> 2, t = lane & 3;
    const int qt = gridDim.x - 1 - blockIdx.x;   // big tiles first
    const int bh = blockIdx.y;
    const int b = bh >> 4, h = bh & 15;
    const size_t base = (size_t)b * SEQ * DIM + (size_t)h * HD;
    const int qrow0 = qt * FQ + warp * 16;

    // Q fragments in registers (scaled by 1/sqrt(64) = 0.125)
    unsigned qf[8][4];
    {
        const float* q0 = xq + base + (size_t)(qrow0 + g) * DIM;
        const float* q1 = xq + base + (size_t)(qrow0 + g + 8) * DIM;
#pragma unroll
        for (int c = 0; c < 8; c++) {
            qf[c][0] = f2tf(q0[8 * c + t] * 0.125f);
            qf[c][1] = f2tf(q1[8 * c + t] * 0.125f);
            qf[c][2] = f2tf(q0[8 * c + t + 4] * 0.125f);
            qf[c][3] = f2tf(q1[8 * c + t + 4] * 0.125f);
        }
    }

    float o[8][4] = {};
    float m0 = -1e30f, m1 = -1e30f, l0 = 0.f, l1 = 0.f;
    unsigned* Pw = Ps + (warp * 16) * LDP;

    const int nkt = qt + 1;
    for (int kt = 0; kt < nkt; kt++) {
        // Load K,V tile (convert to tf32)
        {
            const int r = tid >> 1;
            const int c0 = (tid & 1) * 32;
            const float* kp = xk + base + (size_t)(kt * FK + r) * DIM + c0;
            const float* vp = xv + base + (size_t)(kt * FK + r) * DIM + c0;
            unsigned* kd = Ks + r * LDK + c0;
            unsigned* vd = Vs + r * LDV + c0;
#pragma unroll
            for (int f = 0; f < 8; f++) {
                float4 kk = *(const float4*)(kp + f * 4);
                kd[f * 4 + 0] = f2tf(kk.x); kd[f * 4 + 1] = f2tf(kk.y);
                kd[f * 4 + 2] = f2tf(kk.z); kd[f * 4 + 3] = f2tf(kk.w);
                float4 vv = *(const float4*)(vp + f * 4);
                vd[f * 4 + 0] = f2tf(vv.x); vd[f * 4 + 1] = f2tf(vv.y);
                vd[f * 4 + 2] = f2tf(vv.z); vd[f * 4 + 3] = f2tf(vv.w);
            }
        }
        __syncthreads();

        // S = Q @ K^T (per warp: 16 rows x 64 kv)
        float s[8][4] = {};
#pragma unroll
        for (int c = 0; c < 8; c++) {
#pragma unroll
            for (int nt = 0; nt < 8; nt++) {
                unsigned bfr[2];
                const unsigned* p = Ks + (nt * 8 + g) * LDK + c * 8 + t;
                bfr[0] = p[0];
                bfr[1] = p[4];
                mma_tf32(s[nt], qf[c], bfr);
            }
        }

        // Causal mask (diagonal tile only)
        if (kt == qt) {
            const int rg0 = qrow0 + g, rg1 = qrow0 + g + 8;
#pragma unroll
            for (int nt = 0; nt < 8; nt++) {
                const int col = kt * FK + nt * 8 + 2 * t;
                if (col > rg0)     s[nt][0] = -1e30f;
                if (col + 1 > rg0) s[nt][1] = -1e30f;
                if (col > rg1)     s[nt][2] = -1e30f;
                if (col + 1 > rg1) s[nt][3] = -1e30f;
            }
        }

        // Online softmax (rows g, g+8; quad shuffle reductions)
        float mx0 = -1e30f, mx1 = -1e30f;
#pragma unroll
        for (int nt = 0; nt < 8; nt++) {
            mx0 = fmaxf(mx0, fmaxf(s[nt][0], s[nt][1]));
            mx1 = fmaxf(mx1, fmaxf(s[nt][2], s[nt][3]));
        }
        mx0 = fmaxf(mx0, __shfl_xor_sync(0xffffffffu, mx0, 1));
        mx0 = fmaxf(mx0, __shfl_xor_sync(0xffffffffu, mx0, 2));
        mx1 = fmaxf(mx1, __shfl_xor_sync(0xffffffffu, mx1, 1));
        mx1 = fmaxf(mx1, __shfl_xor_sync(0xffffffffu, mx1, 2));

        const float mn0 = fmaxf(m0, mx0);
        const float mn1 = fmaxf(m1, mx1);
        const float al0 = __expf(m0 - mn0);
        const float al1 = __expf(m1 - mn1);
        m0 = mn0; m1 = mn1;

        float sum0 = 0.f, sum1 = 0.f;
#pragma unroll
        for (int nt = 0; nt < 8; nt++) {
            float p0 = __expf(s[nt][0] - mn0);
            float p1 = __expf(s[nt][1] - mn0);
            float p2 = __expf(s[nt][2] - mn1);
            float p3 = __expf(s[nt][3] - mn1);
            sum0 += p0 + p1;
            sum1 += p2 + p3;
            unsigned* pr0 = Pw + g * LDP + nt * 8 + 2 * t;
            unsigned* pr1 = Pw + (g + 8) * LDP + nt * 8 + 2 * t;
            pr0[0] = f2tf(p0); pr0[1] = f2tf(p1);
            pr1[0] = f2tf(p2); pr1[1] = f2tf(p3);
        }
        sum0 += __shfl_xor_sync(0xffffffffu, sum0, 1);
        sum0 += __shfl_xor_sync(0xffffffffu, sum0, 2);
        sum1 += __shfl_xor_sync(0xffffffffu, sum1, 1);
        sum1 += __shfl_xor_sync(0xffffffffu, sum1, 2);
        l0 = l0 * al0 + sum0;
        l1 = l1 * al1 + sum1;

        // Rescale O
#pragma unroll
        for (int nt = 0; nt < 8; nt++) {
            o[nt][0] *= al0; o[nt][1] *= al0;
            o[nt][2] *= al1; o[nt][3] *= al1;
        }
        __syncwarp();

        // O += P @ V
#pragma unroll
        for (int c = 0; c < 8; c++) {
            unsigned afr[4];
            afr[0] = Pw[g * LDP + c * 8 + t];
            afr[1] = Pw[(g + 8) * LDP + c * 8 + t];
            afr[2] = Pw[g * LDP + c * 8 + t + 4];
            afr[3] = Pw[(g + 8) * LDP + c * 8 + t + 4];
#pragma unroll
            for (int nt = 0; nt < 8; nt++) {
                unsigned bfr[2];
                bfr[0] = Vs[(c * 8 + t) * LDV + nt * 8 + g];
                bfr[1] = Vs[(c * 8 + t + 4) * LDV + nt * 8 + g];
                mma_tf32(o[nt], afr, bfr);
            }
        }
        __syncthreads();   // all warps done with Ks/Vs before next load
    }

    // Normalize and write
    const float inv0 = 1.f / l0, inv1 = 1.f / l1;
#pragma unroll
    for (int nt = 0; nt < 8; nt++) {
        const int col = nt * 8 + 2 * t;
        float* d0 = xo + base + (size_t)(qrow0 + g) * DIM + col;
        float* d1 = xo + base + (size_t)(qrow0 + g + 8) * DIM + col;
        *(float2*)d0 = make_float2(o[nt][0] * inv0, o[nt][1] * inv0);
        *(float2*)d1 = make_float2(o[nt][2] * inv1, o[nt][3] * inv1);
    }
}

// ---------------------------------------------------------------------------
// Launch
// ---------------------------------------------------------------------------
extern "C" void kernel_launch(void* const* d_in, const int* in_sizes, int n_in,
                              void* d_out, int out_size)
{
    const float* q  = (const float*)d_in[0];
    const float* k  = (const float*)d_in[1];
    const float* v  = (const float*)d_in[2];
    const float* wq = (const float*)d_in[3];
    const float* wk = (const float*)d_in[4];
    const float* wv = (const float*)d_in[5];
    const float* wo = (const float*)d_in[6];
    float* out = (float*)d_out;

    float *xq, *xk, *xv, *xo;
    cudaGetSymbolAddress((void**)&xq, g_xq);
    cudaGetSymbolAddress((void**)&xk, g_xk);
    cudaGetSymbolAddress((void**)&xv, g_xv);
    cudaGetSymbolAddress((void**)&xo, g_xo);

    const int fsm = (FK * LDK + FK * LDV + FQ * LDP) * (int)sizeof(unsigned);
    cudaFuncSetAttribute(flash_tc,
                         cudaFuncAttributeMaxDynamicSharedMemorySize, fsm);

    dim3 gemm_grid(DIM / 128, MTOT / 128);   // (8, 32)
    gemm_tc<<<gemm_grid, 256>>>(q, wq, xq, MTOT, DIM, DIM);
    gemm_tc<<<gemm_grid, 256>>>(k, wk, xk, MTOT, DIM, DIM);
    gemm_tc<<<gemm_grid, 256>>>(v, wv, xv, MTOT, DIM, DIM);

    dim3 flash_grid(SEQ / FQ, BATCH * NH);   // (32, 32)
    flash_tc<<<flash_grid, 128, fsm>>>(xq, xk, xv, xo);

    gemm_tc<<<gemm_grid, 256>>>(xo, wo, out, MTOT, DIM, DIM);
}

// round 3
// speedup vs baseline: 2.7793x; 1.1204x over previous
#include <cuda_runtime.h>
#include <math.h>

#define DIM 1024
#define NH 16
#define HD 64
#define BATCH 2
#define SEQ 2048
#define MTOT (BATCH * SEQ)   // 4096

// Scratch (device globals: allowed; no runtime allocation)
__device__ float g_xq[MTOT * DIM];
__device__ float g_xk[MTOT * DIM];
__device__ float g_xv[MTOT * DIM];
__device__ float g_xo[MTOT * DIM];

__device__ __forceinline__ unsigned f2tf(float x) {
    unsigned r;
    asm("cvt.rna.tf32.f32 %0, %1;" : "=r"(r) : "f"(x));
    return r;
}

__device__ __forceinline__ void mma_tf32(float* c, const unsigned* a, const unsigned* b) {
    asm volatile(
        "mma.sync.aligned.m16n8k8.row.col.f32.tf32.tf32.f32 "
        "{%0,%1,%2,%3}, {%4,%5,%6,%7}, {%8,%9}, {%0,%1,%2,%3};\n"
        : "+f"(c[0]), "+f"(c[1]), "+f"(c[2]), "+f"(c[3])
        : "r"(a[0]), "r"(a[1]), "r"(a[2]), "r"(a[3]), "r"(b[0]), "r"(b[1]));
}

__device__ __forceinline__ void cp_async16(void* smem_dst, const void* gptr) {
    unsigned s = (unsigned)__cvta_generic_to_shared(smem_dst);
    asm volatile("cp.async.cg.shared.global [%0], [%1], 16;\n" :: "r"(s), "l"(gptr));
}
__device__ __forceinline__ void cp_commit() {
    asm volatile("cp.async.commit_group;\n");
}
__device__ __forceinline__ void cp_wait0() {
    asm volatile("cp.async.wait_group 0;\n");
}

// ---------------------------------------------------------------------------
// TF32 NT GEMM with cp.async double buffering.
// C[M,N] = A[M,K] @ W[N,K]^T, 128x128x32 tile, 256 threads, warp tile 32x64.
// smem holds raw fp32; cvt.rna applied at fragment load (identical rounding).
// z dimension selects among up to 3 (A, W, C) triples.
// ---------------------------------------------------------------------------
#define GLD 36
#define GEMM_SMEM (2 * 2 * 128 * GLD * 4)   // 73728 bytes

__global__ void __launch_bounds__(256, 2) gemm_tc(
    const float* __restrict__ A0, const float* __restrict__ A1, const float* __restrict__ A2,
    const float* __restrict__ W0, const float* __restrict__ W1, const float* __restrict__ W2,
    float* __restrict__ C0, float* __restrict__ C1, float* __restrict__ C2,
    int M, int N, int K)
{
    extern __shared__ float smg[];
    // stage s: As = smg + s*2*128*GLD, Ws = As + 128*GLD
    const int z = blockIdx.z;
    const float* A = (z == 0) ? A0 : (z == 1) ? A1 : A2;
    const float* W = (z == 0) ? W0 : (z == 1) ? W1 : W2;
    float* C = (z == 0) ? C0 : (z == 1) ? C1 : C2;

    const int tid = threadIdx.x;
    const int warp = tid >> 5, lane = tid & 31;
    const int g = lane >> 2, t = lane & 3;
    const int wm = (warp >> 1) * 32, wn = (warp & 1) * 64;
    const int bm = blockIdx.y * 128, bn = blockIdx.x * 128;

    const int lrow = tid >> 1;            // 0..127
    const int lcol = (tid & 1) * 16;      // 0 or 16
    const float* Ap = A + (size_t)(bm + lrow) * K + lcol;
    const float* Wp = W + (size_t)(bn + lrow) * K + lcol;

    float acc[2][8][4] = {};

    // Prologue: issue stage 0
    {
        float* As = smg;
        float* Ws = As + 128 * GLD;
#pragma unroll
        for (int f = 0; f < 4; f++) {
            cp_async16(As + lrow * GLD + lcol + f * 4, Ap + f * 4);
            cp_async16(Ws + lrow * GLD + lcol + f * 4, Wp + f * 4);
        }
        cp_commit();
    }

    const int niter = K / 32;
    for (int it = 0; it < niter; it++) {
        cp_wait0();
        __syncthreads();

        // Issue next stage (overlaps with compute below)
        if (it + 1 < niter) {
            float* As = smg + ((it + 1) & 1) * 2 * 128 * GLD;
            float* Ws = As + 128 * GLD;
            const int k0 = (it + 1) * 32;
#pragma unroll
            for (int f = 0; f < 4; f++) {
                cp_async16(As + lrow * GLD + lcol + f * 4, Ap + k0 + f * 4);
                cp_async16(Ws + lrow * GLD + lcol + f * 4, Wp + k0 + f * 4);
            }
            cp_commit();
        }

        const float* As = smg + (it & 1) * 2 * 128 * GLD;
        const float* Ws = As + 128 * GLD;

#pragma unroll
        for (int ks = 0; ks < 4; ks++) {
            unsigned afr[2][4], bfr[8][2];
#pragma unroll
            for (int mt = 0; mt < 2; mt++) {
                const float* p = As + (wm + mt * 16 + g) * GLD + ks * 8 + t;
                afr[mt][0] = f2tf(p[0]);
                afr[mt][1] = f2tf(p[8 * GLD]);
                afr[mt][2] = f2tf(p[4]);
                afr[mt][3] = f2tf(p[8 * GLD + 4]);
            }
#pragma unroll
            for (int nt = 0; nt < 8; nt++) {
                const float* p = Ws + (wn + nt * 8 + g) * GLD + ks * 8 + t;
                bfr[nt][0] = f2tf(p[0]);
                bfr[nt][1] = f2tf(p[4]);
            }
#pragma unroll
            for (int mt = 0; mt < 2; mt++)
#pragma unroll
                for (int nt = 0; nt < 8; nt++)
                    mma_tf32(acc[mt][nt], afr[mt], bfr[nt]);
        }
        __syncthreads();   // all warps done with this stage before reuse
    }

#pragma unroll
    for (int mt = 0; mt < 2; mt++)
#pragma unroll
        for (int nt = 0; nt < 8; nt++) {
            const int row = bm + wm + mt * 16 + g;
            const int col = bn + wn + nt * 8 + 2 * t;
            *(float2*)&C[(size_t)row * N + col] =
                make_float2(acc[mt][nt][0], acc[mt][nt][1]);
            *(float2*)&C[(size_t)(row + 8) * N + col] =
                make_float2(acc[mt][nt][2], acc[mt][nt][3]);
        }
}

// ---------------------------------------------------------------------------
// TF32 flash attention, cp.async double-buffered K/V.
// CTA: 64 q-rows (4 warps x 16 rows), KV tiles of 64.
// smem K/V raw fp32 (2 stages), P tile tf32 (per-warp region, syncwarp only).
// ---------------------------------------------------------------------------
#define FQ 64
#define FK 64
#define LDK 68
#define LDV 72
#define LDP 68
#define KBUF (FK * LDK)
#define VBUF (FK * LDV)
#define FLASH_SMEM ((2 * KBUF + 2 * VBUF + FQ * LDP) * 4)   // 89088 bytes

__global__ void __launch_bounds__(128, 2) flash_tc(
    const float* __restrict__ xq, const float* __restrict__ xk,
    const float* __restrict__ xv, float* __restrict__ xo)
{
    extern __shared__ float smf[];
    float* Kst = smf;                    // 2 * KBUF
    float* Vst = Kst + 2 * KBUF;         // 2 * VBUF
    unsigned* Ps = (unsigned*)(Vst + 2 * VBUF);   // FQ * LDP

    const int tid = threadIdx.x;
    const int warp = tid >> 5, lane = tid & 31;
    const int g = lane >> 2, t = lane & 3;
    const int qt = gridDim.x - 1 - blockIdx.x;   // big tiles first
    const int bh = blockIdx.y;
    const int b = bh >> 4, h = bh & 15;
    const size_t base = (size_t)b * SEQ * DIM + (size_t)h * HD;
    const int qrow0 = qt * FQ + warp * 16;

    const int lr = tid >> 1;             // 0..63
    const int lc = (tid & 1) * 32;       // 0 or 32
    const float* kbase = xk + base + (size_t)lr * DIM + lc;
    const float* vbase = xv + base + (size_t)lr * DIM + lc;

    // Prologue: issue K/V tile 0
    {
        float* kd = Kst + lr * LDK + lc;
        float* vd = Vst + lr * LDV + lc;
#pragma unroll
        for (int f = 0; f < 8; f++) {
            cp_async16(kd + f * 4, kbase + f * 4);
            cp_async16(vd + f * 4, vbase + f * 4);
        }
        cp_commit();
    }

    // Q fragments in registers (scaled by 1/8)
    unsigned qf[8][4];
    {
        const float* q0 = xq + base + (size_t)(qrow0 + g) * DIM;
        const float* q1 = xq + base + (size_t)(qrow0 + g + 8) * DIM;
#pragma unroll
        for (int c = 0; c < 8; c++) {
            qf[c][0] = f2tf(q0[8 * c + t] * 0.125f);
            qf[c][1] = f2tf(q1[8 * c + t] * 0.125f);
            qf[c][2] = f2tf(q0[8 * c + t + 4] * 0.125f);
            qf[c][3] = f2tf(q1[8 * c + t + 4] * 0.125f);
        }
    }

    float o[8][4] = {};
    float m0 = -1e30f, m1 = -1e30f, l0 = 0.f, l1 = 0.f;
    unsigned* Pw = Ps + (warp * 16) * LDP;

    const int nkt = qt + 1;
    for (int kt = 0; kt < nkt; kt++) {
        cp_wait0();
        __syncthreads();   // tile kt ready AND previous compute done everywhere

        // Issue tile kt+1 into the other stage (overlaps with compute)
        if (kt + 1 < nkt) {
            float* kd = Kst + ((kt + 1) & 1) * KBUF + lr * LDK + lc;
            float* vd = Vst + ((kt + 1) & 1) * VBUF + lr * LDV + lc;
            const size_t off = (size_t)(kt + 1) * FK * DIM;
#pragma unroll
            for (int f = 0; f < 8; f++) {
                cp_async16(kd + f * 4, kbase + off + f * 4);
                cp_async16(vd + f * 4, vbase + off + f * 4);
            }
            cp_commit();
        }

        const float* Ksf = Kst + (kt & 1) * KBUF;
        const float* Vsf = Vst + (kt & 1) * VBUF;

        // S = Q @ K^T (per warp: 16 rows x 64 kv)
        float s[8][4] = {};
#pragma unroll
        for (int c = 0; c < 8; c++) {
#pragma unroll
            for (int nt = 0; nt < 8; nt++) {
                unsigned bfr[2];
                const float* p = Ksf + (nt * 8 + g) * LDK + c * 8 + t;
                bfr[0] = f2tf(p[0]);
                bfr[1] = f2tf(p[4]);
                mma_tf32(s[nt], qf[c], bfr);
            }
        }

        // Causal mask (diagonal tile only)
        if (kt == qt) {
            const int rg0 = qrow0 + g, rg1 = qrow0 + g + 8;
#pragma unroll
            for (int nt = 0; nt < 8; nt++) {
                const int col = kt * FK + nt * 8 + 2 * t;
                if (col > rg0)     s[nt][0] = -1e30f;
                if (col + 1 > rg0) s[nt][1] = -1e30f;
                if (col > rg1)     s[nt][2] = -1e30f;
                if (col + 1 > rg1) s[nt][3] = -1e30f;
            }
        }

        // Online softmax (rows g, g+8; quad shuffle reductions)
        float mx0 = -1e30f, mx1 = -1e30f;
#pragma unroll
        for (int nt = 0; nt < 8; nt++) {
            mx0 = fmaxf(mx0, fmaxf(s[nt][0], s[nt][1]));
            mx1 = fmaxf(mx1, fmaxf(s[nt][2], s[nt][3]));
        }
        mx0 = fmaxf(mx0, __shfl_xor_sync(0xffffffffu, mx0, 1));
        mx0 = fmaxf(mx0, __shfl_xor_sync(0xffffffffu, mx0, 2));
        mx1 = fmaxf(mx1, __shfl_xor_sync(0xffffffffu, mx1, 1));
        mx1 = fmaxf(mx1, __shfl_xor_sync(0xffffffffu, mx1, 2));

        const float mn0 = fmaxf(m0, mx0);
        const float mn1 = fmaxf(m1, mx1);
        const float al0 = __expf(m0 - mn0);
        const float al1 = __expf(m1 - mn1);
        m0 = mn0; m1 = mn1;

        float sum0 = 0.f, sum1 = 0.f;
#pragma unroll
        for (int nt = 0; nt < 8; nt++) {
            float p0 = __expf(s[nt][0] - mn0);
            float p1 = __expf(s[nt][1] - mn0);
            float p2 = __expf(s[nt][2] - mn1);
            float p3 = __expf(s[nt][3] - mn1);
            sum0 += p0 + p1;
            sum1 += p2 + p3;
            unsigned* pr0 = Pw + g * LDP + nt * 8 + 2 * t;
            unsigned* pr1 = Pw + (g + 8) * LDP + nt * 8 + 2 * t;
            pr0[0] = f2tf(p0); pr0[1] = f2tf(p1);
            pr1[0] = f2tf(p2); pr1[1] = f2tf(p3);
        }
        sum0 += __shfl_xor_sync(0xffffffffu, sum0, 1);
        sum0 += __shfl_xor_sync(0xffffffffu, sum0, 2);
        sum1 += __shfl_xor_sync(0xffffffffu, sum1, 1);
        sum1 += __shfl_xor_sync(0xffffffffu, sum1, 2);
        l0 = l0 * al0 + sum0;
        l1 = l1 * al1 + sum1;

        // Rescale O
#pragma unroll
        for (int nt = 0; nt < 8; nt++) {
            o[nt][0] *= al0; o[nt][1] *= al0;
            o[nt][2] *= al1; o[nt][3] *= al1;
        }
        __syncwarp();

        // O += P @ V
#pragma unroll
        for (int c = 0; c < 8; c++) {
            unsigned afr[4];
            afr[0] = Pw[g * LDP + c * 8 + t];
            afr[1] = Pw[(g + 8) * LDP + c * 8 + t];
            afr[2] = Pw[g * LDP + c * 8 + t + 4];
            afr[3] = Pw[(g + 8) * LDP + c * 8 + t + 4];
#pragma unroll
            for (int nt = 0; nt < 8; nt++) {
                unsigned bfr[2];
                bfr[0] = f2tf(Vsf[(c * 8 + t) * LDV + nt * 8 + g]);
                bfr[1] = f2tf(Vsf[(c * 8 + t + 4) * LDV + nt * 8 + g]);
                mma_tf32(o[nt], afr, bfr);
            }
        }
        // No extra barrier: next iteration's top __syncthreads protects buffers.
    }

    // Normalize and write
    const float inv0 = 1.f / l0, inv1 = 1.f / l1;
#pragma unroll
    for (int nt = 0; nt < 8; nt++) {
        const int col = nt * 8 + 2 * t;
        float* d0 = xo + base + (size_t)(qrow0 + g) * DIM + col;
        float* d1 = xo + base + (size_t)(qrow0 + g + 8) * DIM + col;
        *(float2*)d0 = make_float2(o[nt][0] * inv0, o[nt][1] * inv0);
        *(float2*)d1 = make_float2(o[nt][2] * inv1, o[nt][3] * inv1);
    }
}

// ---------------------------------------------------------------------------
// Launch
// ---------------------------------------------------------------------------
extern "C" void kernel_launch(void* const* d_in, const int* in_sizes, int n_in,
                              void* d_out, int out_size)
{
    const float* q  = (const float*)d_in[0];
    const float* k  = (const float*)d_in[1];
    const float* v  = (const float*)d_in[2];
    const float* wq = (const float*)d_in[3];
    const float* wk = (const float*)d_in[4];
    const float* wv = (const float*)d_in[5];
    const float* wo = (const float*)d_in[6];
    float* out = (float*)d_out;

    float *xq, *xk, *xv, *xo;
    cudaGetSymbolAddress((void**)&xq, g_xq);
    cudaGetSymbolAddress((void**)&xk, g_xk);
    cudaGetSymbolAddress((void**)&xv, g_xv);
    cudaGetSymbolAddress((void**)&xo, g_xo);

    cudaFuncSetAttribute(gemm_tc,
                         cudaFuncAttributeMaxDynamicSharedMemorySize, GEMM_SMEM);
    cudaFuncSetAttribute(flash_tc,
                         cudaFuncAttributeMaxDynamicSharedMemorySize, FLASH_SMEM);

    // Fused QKV projections: grid.z picks (input, weight, output)
    dim3 qkv_grid(DIM / 128, MTOT / 128, 3);   // (8, 32, 3)
    gemm_tc<<<qkv_grid, 256, GEMM_SMEM>>>(q, k, v, wq, wk, wv, xq, xk, xv,
                                          MTOT, DIM, DIM);

    dim3 flash_grid(SEQ / FQ, BATCH * NH);     // (32, 32)
    flash_tc<<<flash_grid, 128, FLASH_SMEM>>>(xq, xk, xv, xo);

    dim3 o_grid(DIM / 128, MTOT / 128, 1);     // (8, 32)
    gemm_tc<<<o_grid, 256, GEMM_SMEM>>>(xo, xo, xo, wo, wo, wo, out, out, out,
                                        MTOT, DIM, DIM);
}

// round 4
// speedup vs baseline: 3.0690x; 1.1043x over previous
#include <cuda_runtime.h>
#include <math.h>

#define DIM 1024
#define NH 16
#define HD 64
#define BATCH 2
#define SEQ 2048
#define MTOT (BATCH * SEQ)   // 4096

// Scratch (device globals: allowed; no runtime allocation)
__device__ float g_xq[MTOT * DIM];
__device__ float g_xk[MTOT * DIM];
__device__ float g_xv[MTOT * DIM];
__device__ float g_xo[MTOT * DIM];
__device__ float g_wr[4 * DIM * DIM];   // tf32-rounded weights (wq,wk,wv,wo)

__device__ __forceinline__ unsigned f2tf(float x) {
    unsigned r;
    asm("cvt.rna.tf32.f32 %0, %1;" : "=r"(r) : "f"(x));
    return r;
}

__device__ __forceinline__ void mma_tf32(float* c, const unsigned* a, const unsigned* b) {
    asm volatile(
        "mma.sync.aligned.m16n8k8.row.col.f32.tf32.tf32.f32 "
        "{%0,%1,%2,%3}, {%4,%5,%6,%7}, {%8,%9}, {%0,%1,%2,%3};\n"
        : "+f"(c[0]), "+f"(c[1]), "+f"(c[2]), "+f"(c[3])
        : "r"(a[0]), "r"(a[1]), "r"(a[2]), "r"(a[3]), "r"(b[0]), "r"(b[1]));
}

__device__ __forceinline__ void ldsm_x4(unsigned& r0, unsigned& r1,
                                        unsigned& r2, unsigned& r3, unsigned addr) {
    asm volatile("ldmatrix.sync.aligned.m8n8.x4.shared.b16 {%0,%1,%2,%3}, [%4];"
                 : "=r"(r0), "=r"(r1), "=r"(r2), "=r"(r3) : "r"(addr));
}

__device__ __forceinline__ void cp_async16(void* smem_dst, const void* gptr) {
    unsigned s = (unsigned)__cvta_generic_to_shared(smem_dst);
    asm volatile("cp.async.cg.shared.global [%0], [%1], 16;\n" :: "r"(s), "l"(gptr));
}
__device__ __forceinline__ void cp_commit() {
    asm volatile("cp.async.commit_group;\n");
}
__device__ __forceinline__ void cp_wait0() {
    asm volatile("cp.async.wait_group 0;\n");
}

// ---------------------------------------------------------------------------
// Pre-round weights to tf32 (bits stored as fp32 with low 13 bits zero).
// grid: (DIM*DIM/4/256, 4), 256 threads; y selects weight matrix.
// ---------------------------------------------------------------------------
__global__ void __launch_bounds__(256) round_w(
    const float4* __restrict__ w0, const float4* __restrict__ w1,
    const float4* __restrict__ w2, const float4* __restrict__ w3,
    float4* __restrict__ dst)
{
    const int y = blockIdx.y;
    const float4* src = (y == 0) ? w0 : (y == 1) ? w1 : (y == 2) ? w2 : w3;
    const int i = blockIdx.x * 256 + threadIdx.x;
    float4 v = src[i];
    float4 r;
    r.x = __uint_as_float(f2tf(v.x));
    r.y = __uint_as_float(f2tf(v.y));
    r.z = __uint_as_float(f2tf(v.z));
    r.w = __uint_as_float(f2tf(v.w));
    dst[(size_t)y * (DIM * DIM / 4) + i] = r;
}

// ---------------------------------------------------------------------------
// TF32 NT GEMM, cp.async double-buffered, ldmatrix fragment loads.
// C[M,N] = A[M,K] @ W[N,K]^T, 128x128x32 tile, 256 threads, warp tile 32x64.
// W must be pre-rounded tf32. A rounded at frag load iff CVT_A.
// Output rounded to tf32 iff ROUND_OUT.
// ---------------------------------------------------------------------------
#define GLD 36
#define GEMM_SMEM (2 * 2 * 128 * GLD * 4)   // 73728 bytes

template <int CVT_A, int ROUND_OUT>
__global__ void __launch_bounds__(256, 2) gemm_tc(
    const float* __restrict__ A0, const float* __restrict__ A1, const float* __restrict__ A2,
    const float* __restrict__ W0, const float* __restrict__ W1, const float* __restrict__ W2,
    float* __restrict__ C0, float* __restrict__ C1, float* __restrict__ C2,
    int M, int N, int K)
{
    extern __shared__ float smg[];
    const int z = blockIdx.z;
    const float* A = (z == 0) ? A0 : (z == 1) ? A1 : A2;
    const float* W = (z == 0) ? W0 : (z == 1) ? W1 : W2;
    float* C = (z == 0) ? C0 : (z == 1) ? C1 : C2;

    const int tid = threadIdx.x;
    const int warp = tid >> 5, lane = tid & 31;
    const int g = lane >> 2, t = lane & 3;
    const int lm = lane >> 3, lr8 = lane & 7;
    const int wm = (warp >> 1) * 32, wn = (warp & 1) * 64;
    const int bm = blockIdx.y * 128, bn = blockIdx.x * 128;

    const int lrow = tid >> 1;
    const int lcol = (tid & 1) * 16;
    const float* Ap = A + (size_t)(bm + lrow) * K + lcol;
    const float* Wp = W + (size_t)(bn + lrow) * K + lcol;

    const unsigned smem_u = (unsigned)__cvta_generic_to_shared(smg);
    // ldmatrix per-lane offsets (in floats)
    // A pattern: row = wm + (lm&1)*8 + lr8, col = (lm>>1)*4
    const unsigned aoff = ((wm + (lm & 1) * 8 + lr8) * GLD + (lm >> 1) * 4) * 4;
    // B pattern: row = wn + (lm>>1)*8 + lr8, col = (lm&1)*4
    const unsigned boff = ((wn + (lm >> 1) * 8 + lr8) * GLD + (lm & 1) * 4) * 4;

    float acc[2][8][4] = {};

    {
        float* As = smg;
        float* Ws = As + 128 * GLD;
#pragma unroll
        for (int f = 0; f < 4; f++) {
            cp_async16(As + lrow * GLD + lcol + f * 4, Ap + f * 4);
            cp_async16(Ws + lrow * GLD + lcol + f * 4, Wp + f * 4);
        }
        cp_commit();
    }

    const int niter = K / 32;
    for (int it = 0; it < niter; it++) {
        cp_wait0();
        __syncthreads();

        if (it + 1 < niter) {
            float* As = smg + ((it + 1) & 1) * 2 * 128 * GLD;
            float* Ws = As + 128 * GLD;
            const int k0 = (it + 1) * 32;
#pragma unroll
            for (int f = 0; f < 4; f++) {
                cp_async16(As + lrow * GLD + lcol + f * 4, Ap + k0 + f * 4);
                cp_async16(Ws + lrow * GLD + lcol + f * 4, Wp + k0 + f * 4);
            }
            cp_commit();
        }

        const unsigned Abase = smem_u + (it & 1) * 2 * 128 * GLD * 4 + aoff;
        const unsigned Wbase = smem_u + ((it & 1) * 2 + 1) * 128 * GLD * 4 + boff;

#pragma unroll
        for (int ks = 0; ks < 4; ks++) {
            unsigned afr[2][4], bfr[8][2];
#pragma unroll
            for (int mt = 0; mt < 2; mt++) {
                ldsm_x4(afr[mt][0], afr[mt][1], afr[mt][2], afr[mt][3],
                        Abase + (mt * 16 * GLD + ks * 8) * 4);
                if (CVT_A) {
#pragma unroll
                    for (int r = 0; r < 4; r++)
                        afr[mt][r] = f2tf(__uint_as_float(afr[mt][r]));
                }
            }
#pragma unroll
            for (int ntp = 0; ntp < 4; ntp++) {
                ldsm_x4(bfr[2 * ntp][0], bfr[2 * ntp][1],
                        bfr[2 * ntp + 1][0], bfr[2 * ntp + 1][1],
                        Wbase + (ntp * 16 * GLD + ks * 8) * 4);
            }
#pragma unroll
            for (int mt = 0; mt < 2; mt++)
#pragma unroll
                for (int nt = 0; nt < 8; nt++)
                    mma_tf32(acc[mt][nt], afr[mt], bfr[nt]);
        }
        __syncthreads();
    }

#pragma unroll
    for (int mt = 0; mt < 2; mt++)
#pragma unroll
        for (int nt = 0; nt < 8; nt++) {
            const int row = bm + wm + mt * 16 + g;
            const int col = bn + wn + nt * 8 + 2 * t;
            float v0 = acc[mt][nt][0], v1 = acc[mt][nt][1];
            float v2 = acc[mt][nt][2], v3 = acc[mt][nt][3];
            if (ROUND_OUT) {
                v0 = __uint_as_float(f2tf(v0)); v1 = __uint_as_float(f2tf(v1));
                v2 = __uint_as_float(f2tf(v2)); v3 = __uint_as_float(f2tf(v3));
            }
            *(float2*)&C[(size_t)row * N + col] = make_float2(v0, v1);
            *(float2*)&C[(size_t)(row + 8) * N + col] = make_float2(v2, v3);
        }
}

// ---------------------------------------------------------------------------
// TF32 flash attention, cp.async double-buffered K/V, ldmatrix K/P frags.
// Inputs xq/xk/xv are pre-rounded tf32 (GEMM epilogue); no cvt in mainloop.
// CTA: 64 q-rows (4 warps x 16 rows), KV tiles of 64.
// ---------------------------------------------------------------------------
#define FQ 64
#define FK 64
#define LDK 68
#define LDV 72
#define LDP 68
#define KBUF (FK * LDK)
#define VBUF (FK * LDV)
#define FLASH_SMEM ((2 * KBUF + 2 * VBUF + FQ * LDP) * 4)   // 89088 bytes

__global__ void __launch_bounds__(128, 2) flash_tc(
    const float* __restrict__ xq, const float* __restrict__ xk,
    const float* __restrict__ xv, float* __restrict__ xo)
{
    extern __shared__ float smf[];
    float* Kst = smf;                    // 2 * KBUF
    float* Vst = Kst + 2 * KBUF;         // 2 * VBUF
    unsigned* Ps = (unsigned*)(Vst + 2 * VBUF);   // FQ * LDP

    const int tid = threadIdx.x;
    const int warp = tid >> 5, lane = tid & 31;
    const int g = lane >> 2, t = lane & 3;
    const int lm = lane >> 3, lr8 = lane & 7;
    const int qt = gridDim.x - 1 - blockIdx.x;
    const int bh = blockIdx.y;
    const int b = bh >> 4, h = bh & 15;
    const size_t base = (size_t)b * SEQ * DIM + (size_t)h * HD;
    const int qrow0 = qt * FQ + warp * 16;

    const unsigned smem_u = (unsigned)__cvta_generic_to_shared(smf);
    // K B-frag ldmatrix offset: row = (lm>>1)*8 + lr8, col = (lm&1)*4
    const unsigned koff = (((lm >> 1) * 8 + lr8) * LDK + (lm & 1) * 4) * 4;
    // P A-frag ldmatrix offset: row = warp*16 + (lm&1)*8 + lr8, col = (lm>>1)*4
    const unsigned poff = (unsigned)((2 * KBUF + 2 * VBUF) * 4) +
        (((warp * 16 + (lm & 1) * 8 + lr8) * LDP + (lm >> 1) * 4) * 4);

    const int lr = tid >> 1;
    const int lc = (tid & 1) * 32;
    const float* kbase = xk + base + (size_t)lr * DIM + lc;
    const float* vbase = xv + base + (size_t)lr * DIM + lc;

    {
        float* kd = Kst + lr * LDK + lc;
        float* vd = Vst + lr * LDV + lc;
#pragma unroll
        for (int f = 0; f < 8; f++) {
            cp_async16(kd + f * 4, kbase + f * 4);
            cp_async16(vd + f * 4, vbase + f * 4);
        }
        cp_commit();
    }

    // Q fragments (pre-rounded tf32; *0.125 is exact so bits stay tf32)
    unsigned qf[8][4];
    {
        const float* q0 = xq + base + (size_t)(qrow0 + g) * DIM;
        const float* q1 = xq + base + (size_t)(qrow0 + g + 8) * DIM;
#pragma unroll
        for (int c = 0; c < 8; c++) {
            qf[c][0] = __float_as_uint(q0[8 * c + t] * 0.125f);
            qf[c][1] = __float_as_uint(q1[8 * c + t] * 0.125f);
            qf[c][2] = __float_as_uint(q0[8 * c + t + 4] * 0.125f);
            qf[c][3] = __float_as_uint(q1[8 * c + t + 4] * 0.125f);
        }
    }

    float o[8][4] = {};
    float m0 = -1e30f, m1 = -1e30f, l0 = 0.f, l1 = 0.f;
    unsigned* Pw = Ps + (warp * 16) * LDP;

    const int nkt = qt + 1;
    for (int kt = 0; kt < nkt; kt++) {
        cp_wait0();
        __syncthreads();

        if (kt + 1 < nkt) {
            float* kd = Kst + ((kt + 1) & 1) * KBUF + lr * LDK + lc;
            float* vd = Vst + ((kt + 1) & 1) * VBUF + lr * LDV + lc;
            const size_t off = (size_t)(kt + 1) * FK * DIM;
#pragma unroll
            for (int f = 0; f < 8; f++) {
                cp_async16(kd + f * 4, kbase + off + f * 4);
                cp_async16(vd + f * 4, vbase + off + f * 4);
            }
            cp_commit();
        }

        const unsigned Kbase = smem_u + (kt & 1) * KBUF * 4 + koff;
        const float* Vsf = Vst + (kt & 1) * VBUF;

        // S = Q @ K^T
        float s[8][4] = {};
#pragma unroll
        for (int c = 0; c < 8; c++) {
            unsigned bfr[8][2];
#pragma unroll
            for (int ntp = 0; ntp < 4; ntp++) {
                ldsm_x4(bfr[2 * ntp][0], bfr[2 * ntp][1],
                        bfr[2 * ntp + 1][0], bfr[2 * ntp + 1][1],
                        Kbase + (ntp * 16 * LDK + c * 8) * 4);
            }
#pragma unroll
            for (int nt = 0; nt < 8; nt++)
                mma_tf32(s[nt], qf[c], bfr[nt]);
        }

        // Causal mask (diagonal tile only)
        if (kt == qt) {
            const int rg0 = qrow0 + g, rg1 = qrow0 + g + 8;
#pragma unroll
            for (int nt = 0; nt < 8; nt++) {
                const int col = kt * FK + nt * 8 + 2 * t;
                if (col > rg0)     s[nt][0] = -1e30f;
                if (col + 1 > rg0) s[nt][1] = -1e30f;
                if (col > rg1)     s[nt][2] = -1e30f;
                if (col + 1 > rg1) s[nt][3] = -1e30f;
            }
        }

        // Online softmax
        float mx0 = -1e30f, mx1 = -1e30f;
#pragma unroll
        for (int nt = 0; nt < 8; nt++) {
            mx0 = fmaxf(mx0, fmaxf(s[nt][0], s[nt][1]));
            mx1 = fmaxf(mx1, fmaxf(s[nt][2], s[nt][3]));
        }
        mx0 = fmaxf(mx0, __shfl_xor_sync(0xffffffffu, mx0, 1));
        mx0 = fmaxf(mx0, __shfl_xor_sync(0xffffffffu, mx0, 2));
        mx1 = fmaxf(mx1, __shfl_xor_sync(0xffffffffu, mx1, 1));
        mx1 = fmaxf(mx1, __shfl_xor_sync(0xffffffffu, mx1, 2));

        const float mn0 = fmaxf(m0, mx0);
        const float mn1 = fmaxf(m1, mx1);
        const float al0 = __expf(m0 - mn0);
        const float al1 = __expf(m1 - mn1);
        m0 = mn0; m1 = mn1;

        float sum0 = 0.f, sum1 = 0.f;
#pragma unroll
        for (int nt = 0; nt < 8; nt++) {
            float p0 = __expf(s[nt][0] - mn0);
            float p1 = __expf(s[nt][1] - mn0);
            float p2 = __expf(s[nt][2] - mn1);
            float p3 = __expf(s[nt][3] - mn1);
            sum0 += p0 + p1;
            sum1 += p2 + p3;
            unsigned* pr0 = Pw + g * LDP + nt * 8 + 2 * t;
            unsigned* pr1 = Pw + (g + 8) * LDP + nt * 8 + 2 * t;
            pr0[0] = f2tf(p0); pr0[1] = f2tf(p1);
            pr1[0] = f2tf(p2); pr1[1] = f2tf(p3);
        }
        sum0 += __shfl_xor_sync(0xffffffffu, sum0, 1);
        sum0 += __shfl_xor_sync(0xffffffffu, sum0, 2);
        sum1 += __shfl_xor_sync(0xffffffffu, sum1, 1);
        sum1 += __shfl_xor_sync(0xffffffffu, sum1, 2);
        l0 = l0 * al0 + sum0;
        l1 = l1 * al1 + sum1;

#pragma unroll
        for (int nt = 0; nt < 8; nt++) {
            o[nt][0] *= al0; o[nt][1] *= al0;
            o[nt][2] *= al1; o[nt][3] *= al1;
        }
        __syncwarp();

        // O += P @ V
#pragma unroll
        for (int c = 0; c < 8; c++) {
            unsigned afr[4];
            ldsm_x4(afr[0], afr[1], afr[2], afr[3], smem_u + poff + (c * 8) * 4);
#pragma unroll
            for (int nt = 0; nt < 8; nt++) {
                unsigned bfr[2];
                bfr[0] = __float_as_uint(Vsf[(c * 8 + t) * LDV + nt * 8 + g]);
                bfr[1] = __float_as_uint(Vsf[(c * 8 + t + 4) * LDV + nt * 8 + g]);
                mma_tf32(o[nt], afr, bfr);
            }
        }
    }

    // Normalize and write (tf32-rounded for the O-projection GEMM)
    const float inv0 = 1.f / l0, inv1 = 1.f / l1;
#pragma unroll
    for (int nt = 0; nt < 8; nt++) {
        const int col = nt * 8 + 2 * t;
        float* d0 = xo + base + (size_t)(qrow0 + g) * DIM + col;
        float* d1 = xo + base + (size_t)(qrow0 + g + 8) * DIM + col;
        *(float2*)d0 = make_float2(__uint_as_float(f2tf(o[nt][0] * inv0)),
                                   __uint_as_float(f2tf(o[nt][1] * inv0)));
        *(float2*)d1 = make_float2(__uint_as_float(f2tf(o[nt][2] * inv1)),
                                   __uint_as_float(f2tf(o[nt][3] * inv1)));
    }
}

// ---------------------------------------------------------------------------
// Launch
// ---------------------------------------------------------------------------
extern "C" void kernel_launch(void* const* d_in, const int* in_sizes, int n_in,
                              void* d_out, int out_size)
{
    const float* q  = (const float*)d_in[0];
    const float* k  = (const float*)d_in[1];
    const float* v  = (const float*)d_in[2];
    const float* wq = (const float*)d_in[3];
    const float* wk = (const float*)d_in[4];
    const float* wv = (const float*)d_in[5];
    const float* wo = (const float*)d_in[6];
    float* out = (float*)d_out;

    float *xq, *xk, *xv, *xo, *wr;
    cudaGetSymbolAddress((void**)&xq, g_xq);
    cudaGetSymbolAddress((void**)&xk, g_xk);
    cudaGetSymbolAddress((void**)&xv, g_xv);
    cudaGetSymbolAddress((void**)&xo, g_xo);
    cudaGetSymbolAddress((void**)&wr, g_wr);

    cudaFuncSetAttribute(gemm_tc<1, 1>,
                         cudaFuncAttributeMaxDynamicSharedMemorySize, GEMM_SMEM);
    cudaFuncSetAttribute(gemm_tc<0, 0>,
                         cudaFuncAttributeMaxDynamicSharedMemorySize, GEMM_SMEM);
    cudaFuncSetAttribute(flash_tc,
                         cudaFuncAttributeMaxDynamicSharedMemorySize, FLASH_SMEM);

    // Pre-round weights to tf32
    dim3 rw_grid(DIM * DIM / 4 / 256, 4);
    round_w<<<rw_grid, 256>>>((const float4*)wq, (const float4*)wk,
                              (const float4*)wv, (const float4*)wo,
                              (float4*)wr);

    const float* wqr = wr;
    const float* wkr = wr + (size_t)DIM * DIM;
    const float* wvr = wr + (size_t)2 * DIM * DIM;
    const float* wor = wr + (size_t)3 * DIM * DIM;

    // Fused QKV projections (A-side cvt, rounded outputs)
    dim3 qkv_grid(DIM / 128, MTOT / 128, 3);
    gemm_tc<1, 1><<<qkv_grid, 256, GEMM_SMEM>>>(q, k, v, wqr, wkr, wvr,
                                                xq, xk, xv, MTOT, DIM, DIM);

    dim3 flash_grid(SEQ / FQ, BATCH * NH);
    flash_tc<<<flash_grid, 128, FLASH_SMEM>>>(xq, xk, xv, xo);

    // O projection (inputs already tf32-rounded; full fp32 output)
    dim3 o_grid(DIM / 128, MTOT / 128, 1);
    gemm_tc<0, 0><<<o_grid, 256, GEMM_SMEM>>>(xo, xo, xo, wor, wor, wor,
                                              out, out, out, MTOT, DIM, DIM);
}

// round 6
// speedup vs baseline: 3.3906x; 1.1048x over previous
#include <cuda_runtime.h>
#include <math.h>

#define DIM 1024
#define NH 16
#define HD 64
#define BATCH 2
#define SEQ 2048
#define MTOT (BATCH * SEQ)   // 4096

// Scratch (device globals: allowed; no runtime allocation)
__device__ float g_xq[MTOT * DIM];
__device__ float g_xk[MTOT * DIM];
__device__ float g_xv[MTOT * DIM];
__device__ float g_xo[MTOT * DIM];
__device__ float g_wr[4 * DIM * DIM];   // tf32-rounded weights (wq,wk,wv,wo)

__device__ __forceinline__ unsigned f2tf(float x) {
    unsigned r;
    asm("cvt.rna.tf32.f32 %0, %1;" : "=r"(r) : "f"(x));
    return r;
}

__device__ __forceinline__ void mma_tf32(float* c, const unsigned* a, const unsigned* b) {
    asm volatile(
        "mma.sync.aligned.m16n8k8.row.col.f32.tf32.tf32.f32 "
        "{%0,%1,%2,%3}, {%4,%5,%6,%7}, {%8,%9}, {%0,%1,%2,%3};\n"
        : "+f"(c[0]), "+f"(c[1]), "+f"(c[2]), "+f"(c[3])
        : "r"(a[0]), "r"(a[1]), "r"(a[2]), "r"(a[3]), "r"(b[0]), "r"(b[1]));
}

__device__ __forceinline__ void ldsm_x4(unsigned& r0, unsigned& r1,
                                        unsigned& r2, unsigned& r3, unsigned addr) {
    asm volatile("ldmatrix.sync.aligned.m8n8.x4.shared.b16 {%0,%1,%2,%3}, [%4];"
                 : "=r"(r0), "=r"(r1), "=r"(r2), "=r"(r3) : "r"(addr));
}

__device__ __forceinline__ void cp_async16(void* smem_dst, const void* gptr) {
    unsigned s = (unsigned)__cvta_generic_to_shared(smem_dst);
    asm volatile("cp.async.cg.shared.global [%0], [%1], 16;\n" :: "r"(s), "l"(gptr));
}
__device__ __forceinline__ void cp_commit() {
    asm volatile("cp.async.commit_group;\n");
}
__device__ __forceinline__ void cp_wait0() {
    asm volatile("cp.async.wait_group 0;\n");
}

// ---------------------------------------------------------------------------
// Pre-round weights to tf32 (bits stored as fp32 with low 13 bits zero).
// ---------------------------------------------------------------------------
__global__ void __launch_bounds__(256) round_w(
    const float4* __restrict__ w0, const float4* __restrict__ w1,
    const float4* __restrict__ w2, const float4* __restrict__ w3,
    float4* __restrict__ dst)
{
    const int y = blockIdx.y;
    const float4* src = (y == 0) ? w0 : (y == 1) ? w1 : (y == 2) ? w2 : w3;
    const int i = blockIdx.x * 256 + threadIdx.x;
    float4 v = src[i];
    float4 r;
    r.x = __uint_as_float(f2tf(v.x));
    r.y = __uint_as_float(f2tf(v.y));
    r.z = __uint_as_float(f2tf(v.z));
    r.w = __uint_as_float(f2tf(v.w));
    dst[(size_t)y * (DIM * DIM / 4) + i] = r;
}

// ---------------------------------------------------------------------------
// TF32 NT GEMM, cp.async double-buffered (ONE barrier per stage), ldmatrix.
// C[M,N] = A[M,K] @ W[N,K]^T, 128x128x32 tile, 256 threads, warp tile 32x64.
// W must be pre-rounded tf32. A rounded at frag load iff CVT_A.
// Output rounded to tf32 iff ROUND_OUT.
// ---------------------------------------------------------------------------
#define GLD 36
#define GEMM_SMEM (2 * 2 * 128 * GLD * 4)   // 73728 bytes

template <int CVT_A, int ROUND_OUT>
__global__ void __launch_bounds__(256, 2) gemm_tc(
    const float* __restrict__ A0, const float* __restrict__ A1, const float* __restrict__ A2,
    const float* __restrict__ W0, const float* __restrict__ W1, const float* __restrict__ W2,
    float* __restrict__ C0, float* __restrict__ C1, float* __restrict__ C2,
    int M, int N, int K)
{
    extern __shared__ float smg[];
    const int z = blockIdx.z;
    const float* A = (z == 0) ? A0 : (z == 1) ? A1 : A2;
    const float* W = (z == 0) ? W0 : (z == 1) ? W1 : W2;
    float* C = (z == 0) ? C0 : (z == 1) ? C1 : C2;

    const int tid = threadIdx.x;
    const int warp = tid >> 5, lane = tid & 31;
    const int g = lane >> 2, t = lane & 3;
    const int lm = lane >> 3, lr8 = lane & 7;
    const int wm = (warp >> 1) * 32, wn = (warp & 1) * 64;
    const int bm = blockIdx.y * 128, bn = blockIdx.x * 128;

    const int lrow = tid >> 1;
    const int lcol = (tid & 1) * 16;
    const float* Ap = A + (size_t)(bm + lrow) * K + lcol;
    const float* Wp = W + (size_t)(bn + lrow) * K + lcol;

    const unsigned smem_u = (unsigned)__cvta_generic_to_shared(smg);
    const unsigned aoff = ((wm + (lm & 1) * 8 + lr8) * GLD + (lm >> 1) * 4) * 4;
    const unsigned boff = ((wn + (lm >> 1) * 8 + lr8) * GLD + (lm & 1) * 4) * 4;

    float acc[2][8][4] = {};

    // Prologue: stage 0
    {
        float* As = smg;
        float* Ws = As + 128 * GLD;
#pragma unroll
        for (int f = 0; f < 4; f++) {
            cp_async16(As + lrow * GLD + lcol + f * 4, Ap + f * 4);
            cp_async16(Ws + lrow * GLD + lcol + f * 4, Wp + f * 4);
        }
        cp_commit();
    }

    const int niter = K / 32;
    for (int it = 0; it < niter; it++) {
        cp_wait0();
        __syncthreads();   // stage `it` visible; all warps done with stage it-1

        // Overwrites buffer (it+1)&1, consumed in iteration it-1: safe.
        if (it + 1 < niter) {
            float* As = smg + ((it + 1) & 1) * 2 * 128 * GLD;
            float* Ws = As + 128 * GLD;
            const int k0 = (it + 1) * 32;
#pragma unroll
            for (int f = 0; f < 4; f++) {
                cp_async16(As + lrow * GLD + lcol + f * 4, Ap + k0 + f * 4);
                cp_async16(Ws + lrow * GLD + lcol + f * 4, Wp + k0 + f * 4);
            }
            cp_commit();
        }

        const unsigned Abase = smem_u + (it & 1) * 2 * 128 * GLD * 4 + aoff;
        const unsigned Wbase = smem_u + ((it & 1) * 2 + 1) * 128 * GLD * 4 + boff;

#pragma unroll
        for (int ks = 0; ks < 4; ks++) {
            unsigned afr[2][4], bfr[8][2];
#pragma unroll
            for (int mt = 0; mt < 2; mt++) {
                ldsm_x4(afr[mt][0], afr[mt][1], afr[mt][2], afr[mt][3],
                        Abase + (mt * 16 * GLD + ks * 8) * 4);
                if (CVT_A) {
#pragma unroll
                    for (int r = 0; r < 4; r++)
                        afr[mt][r] = f2tf(__uint_as_float(afr[mt][r]));
                }
            }
#pragma unroll
            for (int ntp = 0; ntp < 4; ntp++) {
                ldsm_x4(bfr[2 * ntp][0], bfr[2 * ntp][1],
                        bfr[2 * ntp + 1][0], bfr[2 * ntp + 1][1],
                        Wbase + (ntp * 16 * GLD + ks * 8) * 4);
            }
#pragma unroll
            for (int mt = 0; mt < 2; mt++)
#pragma unroll
                for (int nt = 0; nt < 8; nt++)
                    mma_tf32(acc[mt][nt], afr[mt], bfr[nt]);
        }
        // no bottom barrier: next iteration's top barrier protects buffers
    }

#pragma unroll
    for (int mt = 0; mt < 2; mt++)
#pragma unroll
        for (int nt = 0; nt < 8; nt++) {
            const int row = bm + wm + mt * 16 + g;
            const int col = bn + wn + nt * 8 + 2 * t;
            float v0 = acc[mt][nt][0], v1 = acc[mt][nt][1];
            float v2 = acc[mt][nt][2], v3 = acc[mt][nt][3];
            if (ROUND_OUT) {
                v0 = __uint_as_float(f2tf(v0)); v1 = __uint_as_float(f2tf(v1));
                v2 = __uint_as_float(f2tf(v2)); v3 = __uint_as_float(f2tf(v3));
            }
            *(float2*)&C[(size_t)row * N + col] = make_float2(v0, v1);
            *(float2*)&C[(size_t)(row + 8) * N + col] = make_float2(v2, v3);
        }
}

// ---------------------------------------------------------------------------
// TF32 flash attention: FQ=128 q-rows per CTA (8 warps x 16 rows), KV tiles 64.
// Each K/V tile load now feeds 2x the MMAs vs FQ=64. Warps fully above the
// diagonal skip masked tiles. cp.async double-buffered; ldmatrix K/P frags.
// Inputs xq/xk/xv pre-rounded tf32; output xo rounded tf32.
// ---------------------------------------------------------------------------
#define FQ 128
#define FK 64
#define LDK 68
#define LDV 72
#define LDP 68
#define KBUF (FK * LDK)
#define VBUF (FK * LDV)
#define FLASH_SMEM ((2 * KBUF + 2 * VBUF + FQ * LDP) * 4)   // 106496 bytes

__global__ void __launch_bounds__(256, 1) flash_tc(
    const float* __restrict__ xq, const float* __restrict__ xk,
    const float* __restrict__ xv, float* __restrict__ xo)
{
    extern __shared__ float smf[];
    float* Kst = smf;                    // 2 * KBUF
    float* Vst = Kst + 2 * KBUF;         // 2 * VBUF
    unsigned* Ps = (unsigned*)(Vst + 2 * VBUF);   // FQ * LDP

    const int tid = threadIdx.x;
    const int warp = tid >> 5, lane = tid & 31;
    const int g = lane >> 2, t = lane & 3;
    const int lm = lane >> 3, lr8 = lane & 7;
    const int qt = gridDim.x - 1 - blockIdx.x;   // big tiles first
    const int bh = blockIdx.y;
    const int b = bh >> 4, h = bh & 15;
    const size_t base = (size_t)b * SEQ * DIM + (size_t)h * HD;
    const int qrow0 = qt * FQ + warp * 16;

    const unsigned smem_u = (unsigned)__cvta_generic_to_shared(smf);
    const unsigned koff = (((lm >> 1) * 8 + lr8) * LDK + (lm & 1) * 4) * 4;
    const unsigned poff = (unsigned)((2 * KBUF + 2 * VBUF) * 4) +
        (((warp * 16 + (lm & 1) * 8 + lr8) * LDP + (lm >> 1) * 4) * 4);

    // K/V tile loads: 256 threads, 64 rows x 64 cols each
    const int lr = tid >> 2;             // 0..63
    const int lc = (tid & 3) * 16;       // 0,16,32,48
    const float* kbase = xk + base + (size_t)lr * DIM + lc;
    const float* vbase = xv + base + (size_t)lr * DIM + lc;

    {
        float* kd = Kst + lr * LDK + lc;
        float* vd = Vst + lr * LDV + lc;
#pragma unroll
        for (int f = 0; f < 4; f++) {
            cp_async16(kd + f * 4, kbase + f * 4);
            cp_async16(vd + f * 4, vbase + f * 4);
        }
        cp_commit();
    }

    // Q fragments (pre-rounded tf32; *0.125 exact)
    unsigned qf[8][4];
    {
        const float* q0 = xq + base + (size_t)(qrow0 + g) * DIM;
        const float* q1 = xq + base + (size_t)(qrow0 + g + 8) * DIM;
#pragma unroll
        for (int c = 0; c < 8; c++) {
            qf[c][0] = __float_as_uint(q0[8 * c + t] * 0.125f);
            qf[c][1] = __float_as_uint(q1[8 * c + t] * 0.125f);
            qf[c][2] = __float_as_uint(q0[8 * c + t + 4] * 0.125f);
            qf[c][3] = __float_as_uint(q1[8 * c + t + 4] * 0.125f);
        }
    }

    float o[8][4] = {};
    float m0 = -1e30f, m1 = -1e30f, l0 = 0.f, l1 = 0.f;
    unsigned* Pw = Ps + (warp * 16) * LDP;

    const int nkt = 2 * (qt + 1);
    for (int kt = 0; kt < nkt; kt++) {
        cp_wait0();
        __syncthreads();

        if (kt + 1 < nkt) {
            float* kd = Kst + ((kt + 1) & 1) * KBUF + lr * LDK + lc;
            float* vd = Vst + ((kt + 1) & 1) * VBUF + lr * LDV + lc;
            const size_t off = (size_t)(kt + 1) * FK * DIM;
#pragma unroll
            for (int f = 0; f < 4; f++) {
                cp_async16(kd + f * 4, kbase + off + f * 4);
                cp_async16(vd + f * 4, vbase + off + f * 4);
            }
            cp_commit();
        }

        // Fully-masked tile for this warp? (min col > max row)
        if (kt * FK > qrow0 + 15) continue;

        const unsigned Kbase = smem_u + (kt & 1) * KBUF * 4 + koff;
        const float* Vsf = Vst + (kt & 1) * VBUF;

        // S = Q @ K^T
        float s[8][4] = {};
#pragma unroll
        for (int c = 0; c < 8; c++) {
            unsigned bfr[8][2];
#pragma unroll
            for (int ntp = 0; ntp < 4; ntp++) {
                ldsm_x4(bfr[2 * ntp][0], bfr[2 * ntp][1],
                        bfr[2 * ntp + 1][0], bfr[2 * ntp + 1][1],
                        Kbase + (ntp * 16 * LDK + c * 8) * 4);
            }
#pragma unroll
            for (int nt = 0; nt < 8; nt++)
                mma_tf32(s[nt], qf[c], bfr[nt]);
        }

        // Partial mask if tile straddles the diagonal for this warp
        if (kt * FK + FK - 1 > qrow0) {
            const int rg0 = qrow0 + g, rg1 = qrow0 + g + 8;
#pragma unroll
            for (int nt = 0; nt < 8; nt++) {
                const int col = kt * FK + nt * 8 + 2 * t;
                if (col > rg0)     s[nt][0] = -1e30f;
                if (col + 1 > rg0) s[nt][1] = -1e30f;
                if (col > rg1)     s[nt][2] = -1e30f;
                if (col + 1 > rg1) s[nt][3] = -1e30f;
            }
        }

        // Online softmax (rows g, g+8; quad shuffle reductions)
        float mx0 = -1e30f, mx1 = -1e30f;
#pragma unroll
        for (int nt = 0; nt < 8; nt++) {
            mx0 = fmaxf(mx0, fmaxf(s[nt][0], s[nt][1]));
            mx1 = fmaxf(mx1, fmaxf(s[nt][2], s[nt][3]));
        }
        mx0 = fmaxf(mx0, __shfl_xor_sync(0xffffffffu, mx0, 1));
        mx0 = fmaxf(mx0, __shfl_xor_sync(0xffffffffu, mx0, 2));
        mx1 = fmaxf(mx1, __shfl_xor_sync(0xffffffffu, mx1, 1));
        mx1 = fmaxf(mx1, __shfl_xor_sync(0xffffffffu, mx1, 2));

        const float mn0 = fmaxf(m0, mx0);
        const float mn1 = fmaxf(m1, mx1);
        const float al0 = __expf(m0 - mn0);
        const float al1 = __expf(m1 - mn1);
        m0 = mn0; m1 = mn1;

        float sum0 = 0.f, sum1 = 0.f;
#pragma unroll
        for (int nt = 0; nt < 8; nt++) {
            float p0 = __expf(s[nt][0] - mn0);
            float p1 = __expf(s[nt][1] - mn0);
            float p2 = __expf(s[nt][2] - mn1);
            float p3 = __expf(s[nt][3] - mn1);
            sum0 += p0 + p1;
            sum1 += p2 + p3;
            unsigned* pr0 = Pw + g * LDP + nt * 8 + 2 * t;
            unsigned* pr1 = Pw + (g + 8) * LDP + nt * 8 + 2 * t;
            pr0[0] = f2tf(p0); pr0[1] = f2tf(p1);
            pr1[0] = f2tf(p2); pr1[1] = f2tf(p3);
        }
        sum0 += __shfl_xor_sync(0xffffffffu, sum0, 1);
        sum0 += __shfl_xor_sync(0xffffffffu, sum0, 2);
        sum1 += __shfl_xor_sync(0xffffffffu, sum1, 1);
        sum1 += __shfl_xor_sync(0xffffffffu, sum1, 2);
        l0 = l0 * al0 + sum0;
        l1 = l1 * al1 + sum1;

#pragma unroll
        for (int nt = 0; nt < 8; nt++) {
            o[nt][0] *= al0; o[nt][1] *= al0;
            o[nt][2] *= al1; o[nt][3] *= al1;
        }
        __syncwarp();

        // O += P @ V
#pragma unroll
        for (int c = 0; c < 8; c++) {
            unsigned afr[4];
            ldsm_x4(afr[0], afr[1], afr[2], afr[3], smem_u + poff + (c * 8) * 4);
#pragma unroll
            for (int nt = 0; nt < 8; nt++) {
                unsigned bfr[2];
                bfr[0] = __float_as_uint(Vsf[(c * 8 + t) * LDV + nt * 8 + g]);
                bfr[1] = __float_as_uint(Vsf[(c * 8 + t + 4) * LDV + nt * 8 + g]);
                mma_tf32(o[nt], afr, bfr);
            }
        }
    }

    // Normalize and write (tf32-rounded for the O-projection GEMM)
    const float inv0 = 1.f / l0, inv1 = 1.f / l1;
#pragma unroll
    for (int nt = 0; nt < 8; nt++) {
        const int col = nt * 8 + 2 * t;
        float* d0 = xo + base + (size_t)(qrow0 + g) * DIM + col;
        float* d1 = xo + base + (size_t)(qrow0 + g + 8) * DIM + col;
        *(float2*)d0 = make_float2(__uint_as_float(f2tf(o[nt][0] * inv0)),
                                   __uint_as_float(f2tf(o[nt][1] * inv0)));
        *(float2*)d1 = make_float2(__uint_as_float(f2tf(o[nt][2] * inv1)),
                                   __uint_as_float(f2tf(o[nt][3] * inv1)));
    }
}

// ---------------------------------------------------------------------------
// Launch
// ---------------------------------------------------------------------------
extern "C" void kernel_launch(void* const* d_in, const int* in_sizes, int n_in,
                              void* d_out, int out_size)
{
    const float* q  = (const float*)d_in[0];
    const float* k  = (const float*)d_in[1];
    const float* v  = (const float*)d_in[2];
    const float* wq = (const float*)d_in[3];
    const float* wk = (const float*)d_in[4];
    const float* wv = (const float*)d_in[5];
    const float* wo = (const float*)d_in[6];
    float* out = (float*)d_out;

    float *xq, *xk, *xv, *xo, *wr;
    cudaGetSymbolAddress((void**)&xq, g_xq);
    cudaGetSymbolAddress((void**)&xk, g_xk);
    cudaGetSymbolAddress((void**)&xv, g_xv);
    cudaGetSymbolAddress((void**)&xo, g_xo);
    cudaGetSymbolAddress((void**)&wr, g_wr);

    cudaFuncSetAttribute(gemm_tc<1, 1>,
                         cudaFuncAttributeMaxDynamicSharedMemorySize, GEMM_SMEM);
    cudaFuncSetAttribute(gemm_tc<0, 0>,
                         cudaFuncAttributeMaxDynamicSharedMemorySize, GEMM_SMEM);
    cudaFuncSetAttribute(flash_tc,
                         cudaFuncAttributeMaxDynamicSharedMemorySize, FLASH_SMEM);

    // Pre-round weights to tf32
    dim3 rw_grid(DIM * DIM / 4 / 256, 4);
    round_w<<<rw_grid, 256>>>((const float4*)wq, (const float4*)wk,
                              (const float4*)wv, (const float4*)wo,
                              (float4*)wr);

    const float* wqr = wr;
    const float* wkr = wr + (size_t)DIM * DIM;
    const float* wvr = wr + (size_t)2 * DIM * DIM;
    const float* wor = wr + (size_t)3 * DIM * DIM;

    // Fused QKV projections (A-side cvt, rounded outputs)
    dim3 qkv_grid(DIM / 128, MTOT / 128, 3);
    gemm_tc<1, 1><<<qkv_grid, 256, GEMM_SMEM>>>(q, k, v, wqr, wkr, wvr,
                                                xq, xk, xv, MTOT, DIM, DIM);

    dim3 flash_grid(SEQ / FQ, BATCH * NH);   // (16, 32)
    flash_tc<<<flash_grid, 256, FLASH_SMEM>>>(xq, xk, xv, xo);

    // O projection (inputs already tf32-rounded; full fp32 output)
    dim3 o_grid(DIM / 128, MTOT / 128, 1);
    gemm_tc<0, 0><<<o_grid, 256, GEMM_SMEM>>>(xo, xo, xo, wor, wor, wor,
                                              out, out, out, MTOT, DIM, DIM);
}

// round 7
// speedup vs baseline: 3.9680x; 1.1703x over previous
#include <cuda_runtime.h>
#include <math.h>

#define DIM 1024
#define NH 16
#define HD 64
#define BATCH 2
#define SEQ 2048
#define MTOT (BATCH * SEQ)   // 4096

// Scratch (device globals: allowed; no runtime allocation)
__device__ float g_xq[MTOT * DIM];
__device__ float g_xk[MTOT * DIM];
__device__ float g_xv[MTOT * DIM];
__device__ float g_xo[MTOT * DIM];
__device__ float g_wr[4 * DIM * DIM];   // tf32-rounded weights (wq,wk,wv,wo)

__device__ __forceinline__ unsigned f2tf(float x) {
    unsigned r;
    asm("cvt.rna.tf32.f32 %0, %1;" : "=r"(r) : "f"(x));
    return r;
}

__device__ __forceinline__ void mma_tf32(float* c, const unsigned* a, const unsigned* b) {
    asm volatile(
        "mma.sync.aligned.m16n8k8.row.col.f32.tf32.tf32.f32 "
        "{%0,%1,%2,%3}, {%4,%5,%6,%7}, {%8,%9}, {%0,%1,%2,%3};\n"
        : "+f"(c[0]), "+f"(c[1]), "+f"(c[2]), "+f"(c[3])
        : "r"(a[0]), "r"(a[1]), "r"(a[2]), "r"(a[3]), "r"(b[0]), "r"(b[1]));
}

__device__ __forceinline__ void ldsm_x4(unsigned& r0, unsigned& r1,
                                        unsigned& r2, unsigned& r3, unsigned addr) {
    asm volatile("ldmatrix.sync.aligned.m8n8.x4.shared.b16 {%0,%1,%2,%3}, [%4];"
                 : "=r"(r0), "=r"(r1), "=r"(r2), "=r"(r3) : "r"(addr));
}

__device__ __forceinline__ void cp_async16(void* smem_dst, const void* gptr) {
    unsigned s = (unsigned)__cvta_generic_to_shared(smem_dst);
    asm volatile("cp.async.cg.shared.global [%0], [%1], 16;\n" :: "r"(s), "l"(gptr));
}
__device__ __forceinline__ void cp_commit() {
    asm volatile("cp.async.commit_group;\n");
}
__device__ __forceinline__ void cp_wait0() { asm volatile("cp.async.wait_group 0;\n"); }
__device__ __forceinline__ void cp_wait1() { asm volatile("cp.async.wait_group 1;\n"); }

// ---------------------------------------------------------------------------
// Pre-round weights to tf32.
// ---------------------------------------------------------------------------
__global__ void __launch_bounds__(256) round_w(
    const float4* __restrict__ w0, const float4* __restrict__ w1,
    const float4* __restrict__ w2, const float4* __restrict__ w3,
    float4* __restrict__ dst)
{
    const int y = blockIdx.y;
    const float4* src = (y == 0) ? w0 : (y == 1) ? w1 : (y == 2) ? w2 : w3;
    const int i = blockIdx.x * 256 + threadIdx.x;
    float4 v = src[i];
    float4 r;
    r.x = __uint_as_float(f2tf(v.x));
    r.y = __uint_as_float(f2tf(v.y));
    r.z = __uint_as_float(f2tf(v.z));
    r.w = __uint_as_float(f2tf(v.w));
    dst[(size_t)y * (DIM * DIM / 4) + i] = r;
}

// ---------------------------------------------------------------------------
// TF32 NT GEMM, CTA tile 128x256, warp tile 64x64 (8 warps = 2m x 4n),
// 3-stage cp.async pipeline + register fragment double-buffering.
// C[M,N] = A[M,K] @ W[N,K]^T. W pre-rounded tf32; A cvt at frag load iff CVT_A.
// ---------------------------------------------------------------------------
#define GLD 36
#define STG ((128 + 256) * GLD)          // floats per stage (A then B)
#define GEMM_SMEM (3 * STG * 4)          // 165888 bytes

template <int CVT_A, int ROUND_OUT>
__global__ void __launch_bounds__(256, 1) gemm_tc(
    const float* __restrict__ A0, const float* __restrict__ A1, const float* __restrict__ A2,
    const float* __restrict__ W0, const float* __restrict__ W1, const float* __restrict__ W2,
    float* __restrict__ C0, float* __restrict__ C1, float* __restrict__ C2,
    int M, int N, int K)
{
    extern __shared__ float smg[];
    const int z = blockIdx.z;
    const float* A = (z == 0) ? A0 : (z == 1) ? A1 : A2;
    const float* W = (z == 0) ? W0 : (z == 1) ? W1 : W2;
    float* C = (z == 0) ? C0 : (z == 1) ? C1 : C2;

    const int tid = threadIdx.x;
    const int warp = tid >> 5, lane = tid & 31;
    const int g = lane >> 2, t = lane & 3;
    const int lm = lane >> 3, lr8 = lane & 7;
    const int wm = (warp & 1) * 64;          // 2 m-warps
    const int wn = (warp >> 1) * 64;         // 4 n-warps
    const int bm = blockIdx.y * 128, bn = blockIdx.x * 256;

    const unsigned smem_u = (unsigned)__cvta_generic_to_shared(smg);
    const unsigned aoff = ((wm + (lm & 1) * 8 + lr8) * GLD + (lm >> 1) * 4) * 4;
    const unsigned boff = ((wn + (lm >> 1) * 8 + lr8) * GLD + (lm & 1) * 4) * 4;

    float acc[4][8][4] = {};

    // Stage loader: A 128x32 (4 chunks/thread), B 256x32 (8 chunks/thread)
    auto load_stage = [&](int s) {
        float* As = smg + (s % 3) * STG;
        float* Bs = As + 128 * GLD;
        const int k0 = s * 32;
#pragma unroll
        for (int j = 0; j < 4; j++) {
            const int cid = tid + j * 256;
            const int row = cid >> 3, c4 = (cid & 7) * 4;
            cp_async16(As + row * GLD + c4, A + (size_t)(bm + row) * K + k0 + c4);
        }
#pragma unroll
        for (int j = 0; j < 8; j++) {
            const int cid = tid + j * 256;
            const int row = cid >> 3, c4 = (cid & 7) * 4;
            cp_async16(Bs + row * GLD + c4, W + (size_t)(bn + row) * K + k0 + c4);
        }
        cp_commit();
    };

    load_stage(0);
    load_stage(1);

    unsigned afr[2][4][4], bfr[2][8][2];

    const int niter = K / 32;
#pragma unroll 1
    for (int it = 0; it < niter; it++) {
        if (it + 1 < niter) cp_wait1(); else cp_wait0();
        __syncthreads();
        if (it + 2 < niter) load_stage(it + 2);

        const unsigned Ab = smem_u + (it % 3) * STG * 4 + aoff;
        const unsigned Bb = smem_u + ((it % 3) * STG + 128 * GLD) * 4 + boff;

        // ks=0 fragments into buffer 0
#pragma unroll
        for (int mt = 0; mt < 4; mt++) {
            ldsm_x4(afr[0][mt][0], afr[0][mt][1], afr[0][mt][2], afr[0][mt][3],
                    Ab + (mt * 16 * GLD) * 4);
            if (CVT_A) {
#pragma unroll
                for (int r = 0; r < 4; r++)
                    afr[0][mt][r] = f2tf(__uint_as_float(afr[0][mt][r]));
            }
        }
#pragma unroll
        for (int ntp = 0; ntp < 4; ntp++)
            ldsm_x4(bfr[0][2 * ntp][0], bfr[0][2 * ntp][1],
                    bfr[0][2 * ntp + 1][0], bfr[0][2 * ntp + 1][1],
                    Bb + (ntp * 16 * GLD) * 4);

#pragma unroll
        for (int ks = 0; ks < 4; ks++) {
            const int cur = ks & 1, nxt = cur ^ 1;
            if (ks < 3) {
                // prefetch ks+1 fragments (overlaps with MMAs below)
#pragma unroll
                for (int mt = 0; mt < 4; mt++) {
                    ldsm_x4(afr[nxt][mt][0], afr[nxt][mt][1],
                            afr[nxt][mt][2], afr[nxt][mt][3],
                            Ab + (mt * 16 * GLD + (ks + 1) * 8) * 4);
                    if (CVT_A) {
#pragma unroll
                        for (int r = 0; r < 4; r++)
                            afr[nxt][mt][r] = f2tf(__uint_as_float(afr[nxt][mt][r]));
                    }
                }
#pragma unroll
                for (int ntp = 0; ntp < 4; ntp++)
                    ldsm_x4(bfr[nxt][2 * ntp][0], bfr[nxt][2 * ntp][1],
                            bfr[nxt][2 * ntp + 1][0], bfr[nxt][2 * ntp + 1][1],
                            Bb + (ntp * 16 * GLD + (ks + 1) * 8) * 4);
            }
#pragma unroll
            for (int mt = 0; mt < 4; mt++)
#pragma unroll
                for (int nt = 0; nt < 8; nt++)
                    mma_tf32(acc[mt][nt], afr[cur][mt], bfr[cur][nt]);
        }
    }

#pragma unroll
    for (int mt = 0; mt < 4; mt++)
#pragma unroll
        for (int nt = 0; nt < 8; nt++) {
            const int row = bm + wm + mt * 16 + g;
            const int col = bn + wn + nt * 8 + 2 * t;
            float v0 = acc[mt][nt][0], v1 = acc[mt][nt][1];
            float v2 = acc[mt][nt][2], v3 = acc[mt][nt][3];
            if (ROUND_OUT) {
                v0 = __uint_as_float(f2tf(v0)); v1 = __uint_as_float(f2tf(v1));
                v2 = __uint_as_float(f2tf(v2)); v3 = __uint_as_float(f2tf(v3));
            }
            *(float2*)&C[(size_t)row * N + col] = make_float2(v0, v1);
            *(float2*)&C[(size_t)(row + 8) * N + col] = make_float2(v2, v3);
        }
}

// ---------------------------------------------------------------------------
// TF32 flash attention (unchanged from R6): FQ=128, KV tiles 64, cp.async
// double-buffered, ldmatrix K/P frags, warp-local softmax.
// ---------------------------------------------------------------------------
#define FQ 128
#define FK 64
#define LDK 68
#define LDV 72
#define LDP 68
#define KBUF (FK * LDK)
#define VBUF (FK * LDV)
#define FLASH_SMEM ((2 * KBUF + 2 * VBUF + FQ * LDP) * 4)   // 106496 bytes

__global__ void __launch_bounds__(256, 1) flash_tc(
    const float* __restrict__ xq, const float* __restrict__ xk,
    const float* __restrict__ xv, float* __restrict__ xo)
{
    extern __shared__ float smf[];
    float* Kst = smf;
    float* Vst = Kst + 2 * KBUF;
    unsigned* Ps = (unsigned*)(Vst + 2 * VBUF);

    const int tid = threadIdx.x;
    const int warp = tid >> 5, lane = tid & 31;
    const int g = lane >> 2, t = lane & 3;
    const int lm = lane >> 3, lr8 = lane & 7;
    const int qt = gridDim.x - 1 - blockIdx.x;
    const int bh = blockIdx.y;
    const int b = bh >> 4, h = bh & 15;
    const size_t base = (size_t)b * SEQ * DIM + (size_t)h * HD;
    const int qrow0 = qt * FQ + warp * 16;

    const unsigned smem_u = (unsigned)__cvta_generic_to_shared(smf);
    const unsigned koff = (((lm >> 1) * 8 + lr8) * LDK + (lm & 1) * 4) * 4;
    const unsigned poff = (unsigned)((2 * KBUF + 2 * VBUF) * 4) +
        (((warp * 16 + (lm & 1) * 8 + lr8) * LDP + (lm >> 1) * 4) * 4);

    const int lr = tid >> 2;
    const int lc = (tid & 3) * 16;
    const float* kbase = xk + base + (size_t)lr * DIM + lc;
    const float* vbase = xv + base + (size_t)lr * DIM + lc;

    {
        float* kd = Kst + lr * LDK + lc;
        float* vd = Vst + lr * LDV + lc;
#pragma unroll
        for (int f = 0; f < 4; f++) {
            cp_async16(kd + f * 4, kbase + f * 4);
            cp_async16(vd + f * 4, vbase + f * 4);
        }
        cp_commit();
    }

    unsigned qf[8][4];
    {
        const float* q0 = xq + base + (size_t)(qrow0 + g) * DIM;
        const float* q1 = xq + base + (size_t)(qrow0 + g + 8) * DIM;
#pragma unroll
        for (int c = 0; c < 8; c++) {
            qf[c][0] = __float_as_uint(q0[8 * c + t] * 0.125f);
            qf[c][1] = __float_as_uint(q1[8 * c + t] * 0.125f);
            qf[c][2] = __float_as_uint(q0[8 * c + t + 4] * 0.125f);
            qf[c][3] = __float_as_uint(q1[8 * c + t + 4] * 0.125f);
        }
    }

    float o[8][4] = {};
    float m0 = -1e30f, m1 = -1e30f, l0 = 0.f, l1 = 0.f;
    unsigned* Pw = Ps + (warp * 16) * LDP;

    const int nkt = 2 * (qt + 1);
    for (int kt = 0; kt < nkt; kt++) {
        cp_wait0();
        __syncthreads();

        if (kt + 1 < nkt) {
            float* kd = Kst + ((kt + 1) & 1) * KBUF + lr * LDK + lc;
            float* vd = Vst + ((kt + 1) & 1) * VBUF + lr * LDV + lc;
            const size_t off = (size_t)(kt + 1) * FK * DIM;
#pragma unroll
            for (int f = 0; f < 4; f++) {
                cp_async16(kd + f * 4, kbase + off + f * 4);
                cp_async16(vd + f * 4, vbase + off + f * 4);
            }
            cp_commit();
        }

        if (kt * FK > qrow0 + 15) continue;

        const unsigned Kbase = smem_u + (kt & 1) * KBUF * 4 + koff;
        const float* Vsf = Vst + (kt & 1) * VBUF;

        float s[8][4] = {};
#pragma unroll
        for (int c = 0; c < 8; c++) {
            unsigned bfr[8][2];
#pragma unroll
            for (int ntp = 0; ntp < 4; ntp++) {
                ldsm_x4(bfr[2 * ntp][0], bfr[2 * ntp][1],
                        bfr[2 * ntp + 1][0], bfr[2 * ntp + 1][1],
                        Kbase + (ntp * 16 * LDK + c * 8) * 4);
            }
#pragma unroll
            for (int nt = 0; nt < 8; nt++)
                mma_tf32(s[nt], qf[c], bfr[nt]);
        }

        if (kt * FK + FK - 1 > qrow0) {
            const int rg0 = qrow0 + g, rg1 = qrow0 + g + 8;
#pragma unroll
            for (int nt = 0; nt < 8; nt++) {
                const int col = kt * FK + nt * 8 + 2 * t;
                if (col > rg0)     s[nt][0] = -1e30f;
                if (col + 1 > rg0) s[nt][1] = -1e30f;
                if (col > rg1)     s[nt][2] = -1e30f;
                if (col + 1 > rg1) s[nt][3] = -1e30f;
            }
        }

        float mx0 = -1e30f, mx1 = -1e30f;
#pragma unroll
        for (int nt = 0; nt < 8; nt++) {
            mx0 = fmaxf(mx0, fmaxf(s[nt][0], s[nt][1]));
            mx1 = fmaxf(mx1, fmaxf(s[nt][2], s[nt][3]));
        }
        mx0 = fmaxf(mx0, __shfl_xor_sync(0xffffffffu, mx0, 1));
        mx0 = fmaxf(mx0, __shfl_xor_sync(0xffffffffu, mx0, 2));
        mx1 = fmaxf(mx1, __shfl_xor_sync(0xffffffffu, mx1, 1));
        mx1 = fmaxf(mx1, __shfl_xor_sync(0xffffffffu, mx1, 2));

        const float mn0 = fmaxf(m0, mx0);
        const float mn1 = fmaxf(m1, mx1);
        const float al0 = __expf(m0 - mn0);
        const float al1 = __expf(m1 - mn1);
        m0 = mn0; m1 = mn1;

        float sum0 = 0.f, sum1 = 0.f;
#pragma unroll
        for (int nt = 0; nt < 8; nt++) {
            float p0 = __expf(s[nt][0] - mn0);
            float p1 = __expf(s[nt][1] - mn0);
            float p2 = __expf(s[nt][2] - mn1);
            float p3 = __expf(s[nt][3] - mn1);
            sum0 += p0 + p1;
            sum1 += p2 + p3;
            unsigned* pr0 = Pw + g * LDP + nt * 8 + 2 * t;
            unsigned* pr1 = Pw + (g + 8) * LDP + nt * 8 + 2 * t;
            pr0[0] = f2tf(p0); pr0[1] = f2tf(p1);
            pr1[0] = f2tf(p2); pr1[1] = f2tf(p3);
        }
        sum0 += __shfl_xor_sync(0xffffffffu, sum0, 1);
        sum0 += __shfl_xor_sync(0xffffffffu, sum0, 2);
        sum1 += __shfl_xor_sync(0xffffffffu, sum1, 1);
        sum1 += __shfl_xor_sync(0xffffffffu, sum1, 2);
        l0 = l0 * al0 + sum0;
        l1 = l1 * al1 + sum1;

#pragma unroll
        for (int nt = 0; nt < 8; nt++) {
            o[nt][0] *= al0; o[nt][1] *= al0;
            o[nt][2] *= al1; o[nt][3] *= al1;
        }
        __syncwarp();

#pragma unroll
        for (int c = 0; c < 8; c++) {
            unsigned afr[4];
            ldsm_x4(afr[0], afr[1], afr[2], afr[3], smem_u + poff + (c * 8) * 4);
#pragma unroll
            for (int nt = 0; nt < 8; nt++) {
                unsigned bfr[2];
                bfr[0] = __float_as_uint(Vsf[(c * 8 + t) * LDV + nt * 8 + g]);
                bfr[1] = __float_as_uint(Vsf[(c * 8 + t + 4) * LDV + nt * 8 + g]);
                mma_tf32(o[nt], afr, bfr);
            }
        }
    }

    const float inv0 = 1.f / l0, inv1 = 1.f / l1;
#pragma unroll
    for (int nt = 0; nt < 8; nt++) {
        const int col = nt * 8 + 2 * t;
        float* d0 = xo + base + (size_t)(qrow0 + g) * DIM + col;
        float* d1 = xo + base + (size_t)(qrow0 + g + 8) * DIM + col;
        *(float2*)d0 = make_float2(__uint_as_float(f2tf(o[nt][0] * inv0)),
                                   __uint_as_float(f2tf(o[nt][1] * inv0)));
        *(float2*)d1 = make_float2(__uint_as_float(f2tf(o[nt][2] * inv1)),
                                   __uint_as_float(f2tf(o[nt][3] * inv1)));
    }
}

// ---------------------------------------------------------------------------
// Launch
// ---------------------------------------------------------------------------
extern "C" void kernel_launch(void* const* d_in, const int* in_sizes, int n_in,
                              void* d_out, int out_size)
{
    const float* q  = (const float*)d_in[0];
    const float* k  = (const float*)d_in[1];
    const float* v  = (const float*)d_in[2];
    const float* wq = (const float*)d_in[3];
    const float* wk = (const float*)d_in[4];
    const float* wv = (const float*)d_in[5];
    const float* wo = (const float*)d_in[6];
    float* out = (float*)d_out;

    float *xq, *xk, *xv, *xo, *wr;
    cudaGetSymbolAddress((void**)&xq, g_xq);
    cudaGetSymbolAddress((void**)&xk, g_xk);
    cudaGetSymbolAddress((void**)&xv, g_xv);
    cudaGetSymbolAddress((void**)&xo, g_xo);
    cudaGetSymbolAddress((void**)&wr, g_wr);

    cudaFuncSetAttribute(gemm_tc<1, 1>,
                         cudaFuncAttributeMaxDynamicSharedMemorySize, GEMM_SMEM);
    cudaFuncSetAttribute(gemm_tc<0, 0>,
                         cudaFuncAttributeMaxDynamicSharedMemorySize, GEMM_SMEM);
    cudaFuncSetAttribute(flash_tc,
                         cudaFuncAttributeMaxDynamicSharedMemorySize, FLASH_SMEM);

    // Pre-round weights to tf32
    dim3 rw_grid(DIM * DIM / 4 / 256, 4);
    round_w<<<rw_grid, 256>>>((const float4*)wq, (const float4*)wk,
                              (const float4*)wv, (const float4*)wo,
                              (float4*)wr);

    const float* wqr = wr;
    const float* wkr = wr + (size_t)DIM * DIM;
    const float* wvr = wr + (size_t)2 * DIM * DIM;
    const float* wor = wr + (size_t)3 * DIM * DIM;

    // Fused QKV projections (A-side cvt, rounded outputs)
    dim3 qkv_grid(DIM / 256, MTOT / 128, 3);   // (4, 32, 3)
    gemm_tc<1, 1><<<qkv_grid, 256, GEMM_SMEM>>>(q, k, v, wqr, wkr, wvr,
                                                xq, xk, xv, MTOT, DIM, DIM);

    dim3 flash_grid(SEQ / FQ, BATCH * NH);     // (16, 32)
    flash_tc<<<flash_grid, 256, FLASH_SMEM>>>(xq, xk, xv, xo);

    // O projection (inputs already tf32-rounded; full fp32 output)
    dim3 o_grid(DIM / 256, MTOT / 128, 1);     // (4, 32)
    gemm_tc<0, 0><<<o_grid, 256, GEMM_SMEM>>>(xo, xo, xo, wor, wor, wor,
                                              out, out, out, MTOT, DIM, DIM);
}